// round 12
// baseline (speedup 1.0000x reference)
#include <cuda_runtime.h>
#include <cuda_fp16.h>
#include <math.h>
#include <stdint.h>

#define N_NODES 50000
#define N_EDGES 640000
#define D 128
#define H 8

// ---------------- scratch (static device globals; no allocation) ----------------
__device__ float g_x1[N_NODES * D];
__device__ float g_x2[N_NODES * D];
__device__ float g_stats[4 * D];
__device__ float g_bn1[2 * D];
// fp16x2-packed buffers
__device__ uint32_t g_Qh [N_NODES * D / 2];
__device__ uint32_t g_Kh [N_NODES * D / 2];
__device__ uint32_t g_Vh [N_NODES * D / 2];
__device__ uint32_t g_attn[N_NODES * D / 2];
__device__ uint32_t g_hh [N_NODES * D / 2];
__device__ uint32_t g_bx1[N_NODES * D / 2];
__device__ uint32_t g_midh[N_NODES * D];
// CSR
__device__ int g_rowptr[N_NODES + 1];
__device__ int g_cursor[N_NODES];
__device__ int g_csrc[N_EDGES];
__device__ int g_part[256];
// pre-converted weights (fp16)
#define W_TOTAL 131072
__device__ __half g_w[W_TOTAL];
#define OFF_WQ 0
#define OFF_WK 16384
#define OFF_WV 32768
#define OFF_WO 49152
#define OFF_W1 65536
#define OFF_W2 98304

// ---------------- helpers ----------------
__device__ __forceinline__ uint32_t smem_u32(const void* p) {
    uint32_t a;
    asm("{ .reg .u64 t; cvta.to.shared.u64 t, %1; cvt.u32.u64 %0, t; }" : "=r"(a) : "l"(p));
    return a;
}
__device__ __forceinline__ void ldm_x4(uint32_t& a0, uint32_t& a1, uint32_t& a2, uint32_t& a3,
                                       uint32_t addr) {
    asm volatile("ldmatrix.sync.aligned.m8n8.x4.shared.b16 {%0,%1,%2,%3}, [%4];"
                 : "=r"(a0), "=r"(a1), "=r"(a2), "=r"(a3) : "r"(addr));
}
__device__ __forceinline__ void ldm_x2(uint32_t& b0, uint32_t& b1, uint32_t addr) {
    asm volatile("ldmatrix.sync.aligned.m8n8.x2.shared.b16 {%0,%1}, [%2];"
                 : "=r"(b0), "=r"(b1) : "r"(addr));
}
__device__ __forceinline__ void mma_f16(float* c, uint32_t a0, uint32_t a1, uint32_t a2,
                                        uint32_t a3, uint32_t b0, uint32_t b1) {
    asm volatile(
        "mma.sync.aligned.m16n8k16.row.col.f32.f16.f16.f32 "
        "{%0,%1,%2,%3}, {%4,%5,%6,%7}, {%8,%9}, {%0,%1,%2,%3};"
        : "+f"(c[0]), "+f"(c[1]), "+f"(c[2]), "+f"(c[3])
        : "r"(a0), "r"(a1), "r"(a2), "r"(a3), "r"(b0), "r"(b1));
}
__device__ __forceinline__ uint32_t pack_h2(float a, float b) {
    uint32_t r;
    asm("cvt.rn.f16x2.f32 %0, %1, %2;" : "=r"(r) : "f"(b), "f"(a));
    return r;
}
__device__ __forceinline__ void cp16(uint32_t dst, const void* src) {
    asm volatile("cp.async.cg.shared.global [%0], [%1], 16;" :: "r"(dst), "l"(src));
}
__device__ __forceinline__ void cp16z(uint32_t dst, const void* src, bool pred) {
    int sz = pred ? 16 : 0;
    asm volatile("cp.async.cg.shared.global [%0], [%1], 16, %2;"
                 :: "r"(dst), "l"(src), "r"(sz));
}
#define CP_COMMIT() asm volatile("cp.async.commit_group;" ::: "memory")
#define CP_WAIT0()  asm volatile("cp.async.wait_group 0;" ::: "memory")
#define CP_WAIT1()  asm volatile("cp.async.wait_group 1;" ::: "memory")

// ---------------- fused prep ----------------
__global__ void prep_kernel(const float* __restrict__ h,
                            const float* __restrict__ WQ, const float* __restrict__ WK,
                            const float* __restrict__ WV, const float* __restrict__ WO,
                            const float* __restrict__ W1, const float* __restrict__ W2,
                            int npair)
{
    int gid = blockIdx.x * blockDim.x + threadIdx.x;
    if (gid < npair) {
        float2 v = ((const float2*)h)[gid];
        g_hh[gid] = pack_h2(v.x, v.y);
    }
    if (gid < W_TOTAL / 2) {
        int elem = gid * 2;
        const float* src;
        int local;
        if (elem < OFF_W1) {
            int m = elem >> 14;
            local = elem & 16383;
            src = (m == 0) ? WQ : (m == 1) ? WK : (m == 2) ? WV : WO;
        } else if (elem < OFF_W2) {
            local = elem - OFF_W1;
            src = W1;
        } else {
            local = elem - OFF_W2;
            src = W2;
        }
        ((uint32_t*)g_w)[gid] = pack_h2(src[local], src[local + 1]);
    }
    if (gid < N_NODES) g_cursor[gid] = 0;
    if (gid < 4 * D) g_stats[gid] = 0.f;
}

// ---------------- CSR build ----------------
__global__ void hist_kernel(const int* __restrict__ dst, int E) {
    int q = blockIdx.x * blockDim.x + threadIdx.x;
    int e = q * 4;
    if (e + 4 <= E) {
        int4 d4 = *(const int4*)(dst + e);
        atomicAdd(&g_cursor[d4.x], 1);
        atomicAdd(&g_cursor[d4.y], 1);
        atomicAdd(&g_cursor[d4.z], 1);
        atomicAdd(&g_cursor[d4.w], 1);
    } else {
        for (int i = e; i < E; ++i) atomicAdd(&g_cursor[dst[i]], 1);
    }
}

__global__ __launch_bounds__(256) void scan_local(int n) {
    int tid = threadIdx.x;
    int lane = tid & 31;
    int wid = tid >> 5;
    int i = blockIdx.x * 256 + tid;
    int c = (i < n) ? g_cursor[i] : 0;
    int v = c;
#pragma unroll
    for (int o = 1; o < 32; o <<= 1) {
        int t = __shfl_up_sync(0xffffffffu, v, o);
        if (lane >= o) v += t;
    }
    __shared__ int wsum[8];
    if (lane == 31) wsum[wid] = v;
    __syncthreads();
    if (wid == 0 && lane < 8) {
        int w = wsum[lane];
#pragma unroll
        for (int o = 1; o < 8; o <<= 1) {
            int t = __shfl_up_sync(0xffu, w, o);
            if (lane >= o) w += t;
        }
        wsum[lane] = w;
    }
    __syncthreads();
    int off = (wid > 0) ? wsum[wid - 1] : 0;
    if (i < n) g_rowptr[i] = v - c + off;
    if (tid == 255) g_part[blockIdx.x] = v + off;
}

__global__ __launch_bounds__(256) void scan_final(int n, int E) {
    int tid = threadIdx.x;
    int lane = tid & 31;
    int wid = tid >> 5;
    int nb = gridDim.x;
    int p = (tid < nb && tid < (int)blockIdx.x) ? g_part[tid] : 0;
#pragma unroll
    for (int o = 16; o > 0; o >>= 1) p += __shfl_xor_sync(0xffffffffu, p, o);
    __shared__ int wsum[8];
    __shared__ int s_off;
    if (lane == 0) wsum[wid] = p;
    __syncthreads();
    if (tid == 0) {
        int s = 0;
#pragma unroll
        for (int w = 0; w < 8; ++w) s += wsum[w];
        s_off = s;
    }
    __syncthreads();
    int i = blockIdx.x * 256 + tid;
    if (i < n) {
        int r = g_rowptr[i] + s_off;
        g_rowptr[i] = r;
        g_cursor[i] = r;
    }
    if (i == 0) g_rowptr[n] = E;
}

__global__ void scatter_kernel(const int* __restrict__ src, const int* __restrict__ dst, int E) {
    int q = blockIdx.x * blockDim.x + threadIdx.x;
    int e = q * 4;
    if (e + 4 <= E) {
        int4 s4 = *(const int4*)(src + e);
        int4 d4 = *(const int4*)(dst + e);
        g_csrc[atomicAdd(&g_cursor[d4.x], 1)] = s4.x;
        g_csrc[atomicAdd(&g_cursor[d4.y], 1)] = s4.y;
        g_csrc[atomicAdd(&g_cursor[d4.z], 1)] = s4.z;
        g_csrc[atomicAdd(&g_cursor[d4.w], 1)] = s4.w;
    } else {
        for (int i = e; i < E; ++i)
            g_csrc[atomicAdd(&g_cursor[dst[i]], 1)] = src[i];
    }
}

// ---------------- gather attention ----------------
__device__ __forceinline__ float4 unp4(uint2 u) {
    float2 a = __half22float2(*reinterpret_cast<const __half2*>(&u.x));
    float2 b = __half22float2(*reinterpret_cast<const __half2*>(&u.y));
    return make_float4(a.x, a.y, b.x, b.y);
}

__global__ __launch_bounds__(256) void gather_kernel(int n) {
    int warp = (blockIdx.x * blockDim.x + threadIdx.x) >> 5;
    if (warp >= n) return;
    const int lid = threadIdx.x & 31;
    const int d = warp;
    const size_t base = (size_t)d * (D / 2) + lid * 2;

    float4 q = unp4(*(const uint2*)(g_Qh + base));
    float4 acc = make_float4(0.f, 0.f, 0.f, 0.f);
    float zacc = 0.f;

    int beg = g_rowptr[d], end = g_rowptr[d + 1];
    int i = beg;
    for (; i + 2 <= end; i += 2) {
        int s0 = g_csrc[i], s1 = g_csrc[i + 1];
        size_t o0 = (size_t)s0 * (D / 2) + lid * 2;
        size_t o1 = (size_t)s1 * (D / 2) + lid * 2;
        float4 k0 = unp4(*(const uint2*)(g_Kh + o0));
        float4 k1 = unp4(*(const uint2*)(g_Kh + o1));
        float4 v0 = unp4(*(const uint2*)(g_Vh + o0));
        float4 v1 = unp4(*(const uint2*)(g_Vh + o1));
        float p0 = q.x * k0.x + q.y * k0.y + q.z * k0.z + q.w * k0.w;
        float p1 = q.x * k1.x + q.y * k1.y + q.z * k1.z + q.w * k1.w;
        p0 += __shfl_xor_sync(0xffffffffu, p0, 1);
        p1 += __shfl_xor_sync(0xffffffffu, p1, 1);
        p0 += __shfl_xor_sync(0xffffffffu, p0, 2);
        p1 += __shfl_xor_sync(0xffffffffu, p1, 2);
        float sc0 = __expf(fminf(fmaxf(p0 * 0.25f, -5.f), 5.f));
        float sc1 = __expf(fminf(fmaxf(p1 * 0.25f, -5.f), 5.f));
        acc.x += v0.x * sc0 + v1.x * sc1;
        acc.y += v0.y * sc0 + v1.y * sc1;
        acc.z += v0.z * sc0 + v1.z * sc1;
        acc.w += v0.w * sc0 + v1.w * sc1;
        zacc += sc0 + sc1;
    }
    if (i < end) {
        int s0 = g_csrc[i];
        size_t o0 = (size_t)s0 * (D / 2) + lid * 2;
        float4 k0 = unp4(*(const uint2*)(g_Kh + o0));
        float4 v0 = unp4(*(const uint2*)(g_Vh + o0));
        float p0 = q.x * k0.x + q.y * k0.y + q.z * k0.z + q.w * k0.w;
        p0 += __shfl_xor_sync(0xffffffffu, p0, 1);
        p0 += __shfl_xor_sync(0xffffffffu, p0, 2);
        float sc0 = __expf(fminf(fmaxf(p0 * 0.25f, -5.f), 5.f));
        acc.x += v0.x * sc0; acc.y += v0.y * sc0;
        acc.z += v0.z * sc0; acc.w += v0.w * sc0;
        zacc += sc0;
    }
    float inv = 1.0f / zacc;
    *(uint2*)(g_attn + base) = make_uint2(pack_h2(acc.x * inv, acc.y * inv),
                                          pack_h2(acc.z * inv, acc.w * inv));
}

// ---------------- tensor-core GEMM: 64x128 tile, fp16, 2-stage pipeline ----------
enum { EPI_STORE_H = 0, EPI_BIAS_RESID = 1, EPI_BIAS_RELU_H = 2 };

#define TM 64
#define BK 64
#define SK 72
#define TILEA (TM * SK * 2)          // 9216 B
#define TILEW (128 * SK * 2)         // 18432 B
#define STAGE_B (TILEA + TILEW)      // 27648 B
#define DSMEM_BYTES (2 * STAGE_B)    // 55296 B

template <int EPI, bool STATS, bool RESBN, int KT>
__device__ __forceinline__ void tgemm_core(
    const __half* __restrict__ A, const __half* __restrict__ W,
    const float* __restrict__ bias, const float* __restrict__ resid,
    const float* __restrict__ t0, const float* __restrict__ t1,
    float* __restrict__ ssum, float* __restrict__ ssq,
    float* __restrict__ Cf, uint32_t* __restrict__ Ch,
    int M, int ldc, int rowBase, int colBase)
{
    extern __shared__ __align__(16) char sm[];
    const uint32_t smbase = smem_u32(sm);

    const int tid = threadIdx.x;
    const int wid = tid >> 5;
    const int lid = tid & 31;
    const int warp_m = wid & 1;    // 2 x 32 rows
    const int warp_n = wid >> 1;   // 4 x 32 cols

    const int ar = (lid & 7) + ((lid >> 3) & 1) * 8;
    const int ac = (lid >> 4) * 8;
    const int br = lid & 7;
    const int bc = ((lid >> 3) & 1) * 8;

    const uint32_t aOff = (uint32_t)((warp_m * 32 + ar) * SK + ac) * 2;
    const uint32_t bOff = (uint32_t)((warp_n * 32 + br) * SK + bc) * 2;

    float acc[2][4][4];
#pragma unroll
    for (int i = 0; i < 2; ++i)
#pragma unroll
        for (int j = 0; j < 4; ++j)
#pragma unroll
            for (int t = 0; t < 4; ++t) acc[i][j][t] = 0.f;

    // A loader: 64 rows, 4 quarters of 16 fp16
    const int arow = tid >> 2;
    const int aq = tid & 3;
    const int grow = rowBase + arow;
    const bool avalid = grow < M;
    const __half* pA = A + (size_t)grow * KT + aq * 16;
    const uint32_t sdstA = (uint32_t)(arow * SK + aq * 16) * 2;
    // W loader: 128 rows, 2 halves of 32 fp16
    const int wrow = tid >> 1;
    const int wh2 = tid & 1;
    const __half* pW = W + (size_t)(colBase + wrow) * KT + wh2 * 32;
    const uint32_t sdstW = (uint32_t)(wrow * SK + wh2 * 32) * 2;

    auto load_slab = [&](int slab, int stage) {
        uint32_t sb = smbase + stage * STAGE_B;
        const __half* a = pA + slab * BK;
        cp16z(sb + sdstA, a, avalid);
        cp16z(sb + sdstA + 16, a + 8, avalid);
        const __half* w = pW + slab * BK;
        uint32_t wb = sb + TILEA + sdstW;
#pragma unroll
        for (int c = 0; c < 4; ++c) cp16(wb + c * 16, w + c * 8);
        CP_COMMIT();
    };

    constexpr int NSLAB = KT / BK;
    load_slab(0, 0);
#pragma unroll
    for (int s = 0; s < NSLAB; ++s) {
        if (s + 1 < NSLAB) {
            load_slab(s + 1, (s + 1) & 1);
            CP_WAIT1();
        } else {
            CP_WAIT0();
        }
        __syncthreads();

        const uint32_t stA = smbase + (s & 1) * STAGE_B;
        const uint32_t stW = stA + TILEA;
#pragma unroll
        for (int ks = 0; ks < 4; ++ks) {
            const uint32_t k0 = (uint32_t)(ks * 16) * 2;
            uint32_t bh[4][2];
#pragma unroll
            for (int j = 0; j < 4; ++j)
                ldm_x2(bh[j][0], bh[j][1], stW + bOff + (uint32_t)(j * 8 * SK) * 2 + k0);
#pragma unroll
            for (int i = 0; i < 2; ++i) {
                uint32_t a0, a1, a2, a3;
                ldm_x4(a0, a1, a2, a3, stA + aOff + (uint32_t)(i * 16 * SK) * 2 + k0);
#pragma unroll
                for (int j = 0; j < 4; ++j)
                    mma_f16(acc[i][j], a0, a1, a2, a3, bh[j][0], bh[j][1]);
            }
        }
        if (s + 1 < NSLAB) __syncthreads();
    }

    // ---- epilogue ----
    const int rr = lid >> 2;
    const int cc = (lid & 3) * 2;
    float cs[8], cq[8];
    if (STATS) {
#pragma unroll
        for (int t = 0; t < 8; ++t) { cs[t] = 0.f; cq[t] = 0.f; }
    }
#pragma unroll
    for (int i = 0; i < 2; ++i) {
#pragma unroll
        for (int hf = 0; hf < 2; ++hf) {
            int r = rowBase + warp_m * 32 + i * 16 + rr + hf * 8;
            if (r >= M) continue;
#pragma unroll
            for (int j = 0; j < 4; ++j) {
                int col = colBase + warp_n * 32 + j * 8 + cc;
                float v0 = acc[i][j][hf * 2];
                float v1 = acc[i][j][hf * 2 + 1];
                if (EPI == EPI_BIAS_RESID) {
                    v0 += bias[col];
                    v1 += bias[col + 1];
                    float r0 = resid[(size_t)r * D + col];
                    float r1 = resid[(size_t)r * D + col + 1];
                    if (RESBN) {
                        r0 = r0 * t0[col] + t1[col];
                        r1 = r1 * t0[col + 1] + t1[col + 1];
                    }
                    v0 += r0; v1 += r1;
                } else if (EPI == EPI_BIAS_RELU_H) {
                    v0 = fmaxf(v0 + bias[col], 0.f);
                    v1 = fmaxf(v1 + bias[col + 1], 0.f);
                }
                if (STATS) {
                    cs[j * 2] += v0;     cq[j * 2] += v0 * v0;
                    cs[j * 2 + 1] += v1; cq[j * 2 + 1] += v1 * v1;
                }
                if (EPI == EPI_BIAS_RESID) {
                    *(float2*)(Cf + (size_t)r * ldc + col) = make_float2(v0, v1);
                } else {
                    Ch[((size_t)r * ldc + col) >> 1] = pack_h2(v0, v1);
                }
            }
        }
    }
    if (STATS) {
#pragma unroll
        for (int t = 0; t < 8; ++t) {
#pragma unroll
            for (int o = 4; o < 32; o <<= 1) {
                cs[t] += __shfl_xor_sync(0xffffffffu, cs[t], o);
                cq[t] += __shfl_xor_sync(0xffffffffu, cq[t], o);
            }
        }
        if (lid < 4) {
#pragma unroll
            for (int t = 0; t < 8; ++t) {
                int col = colBase + warp_n * 32 + (t >> 1) * 8 + lid * 2 + (t & 1);
                atomicAdd(&ssum[col & (D - 1)], cs[t]);
                atomicAdd(&ssq[col & (D - 1)], cq[t]);
            }
        }
    }
}

template <int EPI, bool STATS, bool RESBN, int KT>
__global__ __launch_bounds__(256, 3) void tgemm_k(
    const __half* __restrict__ A, const __half* __restrict__ W,
    const float* __restrict__ bias, const float* __restrict__ resid,
    const float* __restrict__ t0, const float* __restrict__ t1,
    float* __restrict__ ssum, float* __restrict__ ssq,
    float* __restrict__ Cf, uint32_t* __restrict__ Ch, int M, int ldc)
{
    tgemm_core<EPI, STATS, RESBN, KT>(A, W, bias, resid, t0, t1, ssum, ssq, Cf, Ch,
                                      M, ldc, blockIdx.x * TM, blockIdx.y * 128);
}

__global__ __launch_bounds__(256, 3) void qkv_kernel(int M) {
    int off = (blockIdx.y == 0) ? OFF_WQ : (blockIdx.y == 1) ? OFF_WK : OFF_WV;
    uint32_t* C = (blockIdx.y == 0) ? g_Qh : (blockIdx.y == 1) ? g_Kh : g_Vh;
    tgemm_core<EPI_STORE_H, false, false, 128>(
        (const __half*)g_hh, g_w + off, nullptr, nullptr, nullptr, nullptr,
        nullptr, nullptr, nullptr, C, M, D, blockIdx.x * TM, 0);
}

// ---------------- BN1: fused finalize + convert ----------------
__global__ __launch_bounds__(256) void bn_convert(
    const float* __restrict__ x1, const float* __restrict__ sum, const float* __restrict__ sq,
    const float* __restrict__ g, const float* __restrict__ b,
    float* __restrict__ bn_out, int npair, int M)
{
    __shared__ float s_sc[D], s_sh[D];
    int tid = threadIdx.x;
    if (tid < D) {
        float invM = 1.0f / (float)M;
        float mu = sum[tid] * invM;
        float var = sq[tid] * invM - mu * mu;
        float sc = g[tid] * rsqrtf(var + 1e-5f);
        s_sc[tid] = sc;
        s_sh[tid] = b[tid] - mu * sc;
        if (blockIdx.x == 0) {
            bn_out[tid] = sc;
            bn_out[D + tid] = s_sh[tid];
        }
    }
    __syncthreads();
    int p = blockIdx.x * blockDim.x + tid;
    if (p >= npair) return;
    float2 v = ((const float2*)x1)[p];
    int col = (p * 2) & (D - 1);
    g_bx1[p] = pack_h2(v.x * s_sc[col] + s_sh[col], v.y * s_sc[col + 1] + s_sh[col + 1]);
}

// bn_apply with inline BN2 finalize + float4 I/O
__global__ __launch_bounds__(256) void bn_apply(
    const float* __restrict__ x, const float* __restrict__ sum, const float* __restrict__ sq,
    const float* __restrict__ g, const float* __restrict__ b,
    float* __restrict__ out, int M)
{
    __shared__ float s_sc[D], s_sh[D];
    int tid = threadIdx.x;
    if (tid < D) {
        float invM = 1.0f / (float)M;
        float mu = sum[tid] * invM;
        float var = sq[tid] * invM - mu * mu;
        float sc = g[tid] * rsqrtf(var + 1e-5f);
        s_sc[tid] = sc;
        s_sh[tid] = b[tid] - mu * sc;
    }
    __syncthreads();
    int total4 = M * D / 4;
    int stride = gridDim.x * blockDim.x;
    for (int i = blockIdx.x * blockDim.x + tid; i < total4; i += stride) {
        float4 v = ((const float4*)x)[i];
        int col = (i * 4) & (D - 1);
        v.x = v.x * s_sc[col] + s_sh[col];
        v.y = v.y * s_sc[col + 1] + s_sh[col + 1];
        v.z = v.z * s_sc[col + 2] + s_sh[col + 2];
        v.w = v.w * s_sc[col + 3] + s_sh[col + 3];
        ((float4*)out)[i] = v;
    }
}

// ---------------- host launch ----------------
extern "C" void kernel_launch(void* const* d_in, const int* in_sizes, int n_in,
                              void* d_out, int out_size)
{
    const float* h    = (const float*)d_in[0];
    const int*   src  = (const int*)d_in[1];
    const int*   dst  = (const int*)d_in[2];
    const float* WQ   = (const float*)d_in[3];
    const float* WK   = (const float*)d_in[4];
    const float* WV   = (const float*)d_in[5];
    const float* WO   = (const float*)d_in[6];
    const float* bO   = (const float*)d_in[7];
    const float* W1   = (const float*)d_in[8];
    const float* b1   = (const float*)d_in[9];
    const float* W2   = (const float*)d_in[10];
    const float* b2   = (const float*)d_in[11];
    const float* bn1g = (const float*)d_in[12];
    const float* bn1b = (const float*)d_in[13];
    const float* bn2g = (const float*)d_in[14];
    const float* bn2b = (const float*)d_in[15];
    float* out = (float*)d_out;

    int M = in_sizes[0] / D;
    int E = in_sizes[1];
    if (M > N_NODES) M = N_NODES;
    if (E > N_EDGES) E = N_EDGES;

    float *x1p, *x2p, *stp, *bn1p;
    uint32_t *attnp, *bx1p, *midp;
    __half *wp;
    cudaGetSymbolAddress((void**)&x1p, g_x1);
    cudaGetSymbolAddress((void**)&x2p, g_x2);
    cudaGetSymbolAddress((void**)&stp, g_stats);
    cudaGetSymbolAddress((void**)&bn1p, g_bn1);
    cudaGetSymbolAddress((void**)&attnp, g_attn);
    cudaGetSymbolAddress((void**)&bx1p, g_bx1);
    cudaGetSymbolAddress((void**)&midp, g_midh);
    cudaGetSymbolAddress((void**)&wp, g_w);

    cudaFuncSetAttribute(qkv_kernel, cudaFuncAttributeMaxDynamicSharedMemorySize, DSMEM_BYTES);
    cudaFuncSetAttribute(tgemm_k<EPI_BIAS_RESID, true, false, 128>,
                         cudaFuncAttributeMaxDynamicSharedMemorySize, DSMEM_BYTES);
    cudaFuncSetAttribute(tgemm_k<EPI_BIAS_RELU_H, false, false, 128>,
                         cudaFuncAttributeMaxDynamicSharedMemorySize, DSMEM_BYTES);
    cudaFuncSetAttribute(tgemm_k<EPI_BIAS_RESID, true, true, 256>,
                         cudaFuncAttributeMaxDynamicSharedMemorySize, DSMEM_BYTES);

    dim3 blk(256);
    int gx = (M + TM - 1) / TM;
    int nb = (M + 255) / 256;
    int npair = M * D / 2;
    int cvb = (npair + 255) / 256;
    int e4 = (E + 3) / 4;

    prep_kernel<<<cvb, 256>>>(h, WQ, WK, WV, WO, W1, W2, npair);

    hist_kernel<<<(e4 + 255) / 256, 256>>>(dst, E);
    scan_local<<<nb, 256>>>(M);
    scan_final<<<nb, 256>>>(M, E);
    scatter_kernel<<<(e4 + 255) / 256, 256>>>(src, dst, E);

    qkv_kernel<<<dim3(gx, 3), blk, DSMEM_BYTES>>>(M);

    gather_kernel<<<(M * 32 + 255) / 256, 256>>>(M);

    tgemm_k<EPI_BIAS_RESID, true, false, 128><<<dim3(gx, 1), blk, DSMEM_BYTES>>>(
        (const __half*)attnp, wp + OFF_WO, bO, h, nullptr, nullptr,
        stp, stp + D, x1p, nullptr, M, D);

    bn_convert<<<cvb, 256>>>(x1p, stp, stp + D, bn1g, bn1b, bn1p, npair, M);

    tgemm_k<EPI_BIAS_RELU_H, false, false, 128><<<dim3(gx, 2), blk, DSMEM_BYTES>>>(
        (const __half*)bx1p, wp + OFF_W1, b1, nullptr, nullptr, nullptr,
        nullptr, nullptr, nullptr, midp, M, 2 * D);

    tgemm_k<EPI_BIAS_RESID, true, true, 256><<<dim3(gx, 1), blk, DSMEM_BYTES>>>(
        (const __half*)midp, wp + OFF_W2, b2, x1p, bn1p, bn1p + D,
        stp + 2 * D, stp + 3 * D, x2p, nullptr, M, D);

    bn_apply<<<1024, 256>>>(x2p, stp + 2 * D, stp + 3 * D, bn2g, bn2b, out, M);
}

// round 13
// speedup vs baseline: 1.5743x; 1.5743x over previous
#include <cuda_runtime.h>
#include <cuda_fp16.h>
#include <math.h>
#include <stdint.h>

#define N_NODES 50000
#define N_EDGES 640000
#define D 128
#define H 8

// ---------------- scratch (static device globals; no allocation) ----------------
__device__ float g_x1[N_NODES * D];
__device__ float g_x2[N_NODES * D];
__device__ float g_stats[4 * D];
__device__ float g_bn1[2 * D];
// fp16x2-packed buffers
__device__ uint32_t g_Qh [N_NODES * D / 2];
__device__ uint32_t g_Kh [N_NODES * D / 2];
__device__ uint32_t g_Vh [N_NODES * D / 2];
__device__ uint32_t g_attn[N_NODES * D / 2];
__device__ uint32_t g_hh [N_NODES * D / 2];
__device__ uint32_t g_bx1[N_NODES * D / 2];
__device__ uint32_t g_midh[N_NODES * D];
// CSR
__device__ int g_rowptr[N_NODES + 1];
__device__ int g_cursor[N_NODES];
__device__ int g_csrc[N_EDGES];
__device__ int g_part[256];
// pre-converted weights (fp16)
#define W_TOTAL 131072
__device__ __half g_w[W_TOTAL];
#define OFF_WQ 0
#define OFF_WK 16384
#define OFF_WV 32768
#define OFF_WO 49152
#define OFF_W1 65536
#define OFF_W2 98304

// ---------------- helpers ----------------
__device__ __forceinline__ uint32_t smem_u32(const void* p) {
    uint32_t a;
    asm("{ .reg .u64 t; cvta.to.shared.u64 t, %1; cvt.u32.u64 %0, t; }" : "=r"(a) : "l"(p));
    return a;
}
__device__ __forceinline__ void ldm_x4(uint32_t& a0, uint32_t& a1, uint32_t& a2, uint32_t& a3,
                                       uint32_t addr) {
    asm volatile("ldmatrix.sync.aligned.m8n8.x4.shared.b16 {%0,%1,%2,%3}, [%4];"
                 : "=r"(a0), "=r"(a1), "=r"(a2), "=r"(a3) : "r"(addr));
}
__device__ __forceinline__ void ldm_x2(uint32_t& b0, uint32_t& b1, uint32_t addr) {
    asm volatile("ldmatrix.sync.aligned.m8n8.x2.shared.b16 {%0,%1}, [%2];"
                 : "=r"(b0), "=r"(b1) : "r"(addr));
}
__device__ __forceinline__ void mma_f16(float* c, uint32_t a0, uint32_t a1, uint32_t a2,
                                        uint32_t a3, uint32_t b0, uint32_t b1) {
    asm volatile(
        "mma.sync.aligned.m16n8k16.row.col.f32.f16.f16.f32 "
        "{%0,%1,%2,%3}, {%4,%5,%6,%7}, {%8,%9}, {%0,%1,%2,%3};"
        : "+f"(c[0]), "+f"(c[1]), "+f"(c[2]), "+f"(c[3])
        : "r"(a0), "r"(a1), "r"(a2), "r"(a3), "r"(b0), "r"(b1));
}
__device__ __forceinline__ uint32_t pack_h2(float a, float b) {
    uint32_t r;
    asm("cvt.rn.f16x2.f32 %0, %1, %2;" : "=r"(r) : "f"(b), "f"(a));
    return r;
}
__device__ __forceinline__ void cp16(uint32_t dst, const void* src) {
    asm volatile("cp.async.cg.shared.global [%0], [%1], 16;" :: "r"(dst), "l"(src));
}
__device__ __forceinline__ void cp16z(uint32_t dst, const void* src, bool pred) {
    int sz = pred ? 16 : 0;
    asm volatile("cp.async.cg.shared.global [%0], [%1], 16, %2;"
                 :: "r"(dst), "l"(src), "r"(sz));
}
#define CP_COMMIT() asm volatile("cp.async.commit_group;" ::: "memory")
#define CP_WAIT0()  asm volatile("cp.async.wait_group 0;" ::: "memory")
#define CP_WAIT1()  asm volatile("cp.async.wait_group 1;" ::: "memory")

// ---------------- fused prep: zero + weight convert + h convert ----------------
__global__ void prep_kernel(const float* __restrict__ h,
                            const float* __restrict__ WQ, const float* __restrict__ WK,
                            const float* __restrict__ WV, const float* __restrict__ WO,
                            const float* __restrict__ W1, const float* __restrict__ W2,
                            int npair)
{
    int gid = blockIdx.x * blockDim.x + threadIdx.x;
    if (gid < npair) {
        float2 v = ((const float2*)h)[gid];
        g_hh[gid] = pack_h2(v.x, v.y);
    }
    if (gid < W_TOTAL / 2) {
        int elem = gid * 2;
        const float* src;
        int local;
        if (elem < OFF_W1) {
            int m = elem >> 14;
            local = elem & 16383;
            src = (m == 0) ? WQ : (m == 1) ? WK : (m == 2) ? WV : WO;
        } else if (elem < OFF_W2) {
            local = elem - OFF_W1;
            src = W1;
        } else {
            local = elem - OFF_W2;
            src = W2;
        }
        ((uint32_t*)g_w)[gid] = pack_h2(src[local], src[local + 1]);
    }
    if (gid < N_NODES) g_cursor[gid] = 0;
    if (gid < 4 * D) g_stats[gid] = 0.f;
}

// ---------------- CSR build ----------------
__global__ void hist_kernel(const int* __restrict__ dst, int E) {
    int q = blockIdx.x * blockDim.x + threadIdx.x;
    int e = q * 4;
    if (e + 4 <= E) {
        int4 d4 = *(const int4*)(dst + e);
        atomicAdd(&g_cursor[d4.x], 1);
        atomicAdd(&g_cursor[d4.y], 1);
        atomicAdd(&g_cursor[d4.z], 1);
        atomicAdd(&g_cursor[d4.w], 1);
    } else {
        for (int i = e; i < E; ++i) atomicAdd(&g_cursor[dst[i]], 1);
    }
}

__global__ __launch_bounds__(256) void scan_local(int n) {
    int tid = threadIdx.x;
    int lane = tid & 31;
    int wid = tid >> 5;
    int i = blockIdx.x * 256 + tid;
    int c = (i < n) ? g_cursor[i] : 0;
    int v = c;
#pragma unroll
    for (int o = 1; o < 32; o <<= 1) {
        int t = __shfl_up_sync(0xffffffffu, v, o);
        if (lane >= o) v += t;
    }
    __shared__ int wsum[8];
    if (lane == 31) wsum[wid] = v;
    __syncthreads();
    if (wid == 0 && lane < 8) {
        int w = wsum[lane];
#pragma unroll
        for (int o = 1; o < 8; o <<= 1) {
            int t = __shfl_up_sync(0xffu, w, o);
            if (lane >= o) w += t;
        }
        wsum[lane] = w;
    }
    __syncthreads();
    int off = (wid > 0) ? wsum[wid - 1] : 0;
    if (i < n) g_rowptr[i] = v - c + off;
    if (tid == 255) g_part[blockIdx.x] = v + off;
}

__global__ __launch_bounds__(256) void scan_final(int n, int E) {
    int tid = threadIdx.x;
    int lane = tid & 31;
    int wid = tid >> 5;
    int nb = gridDim.x;
    int p = (tid < nb && tid < (int)blockIdx.x) ? g_part[tid] : 0;
#pragma unroll
    for (int o = 16; o > 0; o >>= 1) p += __shfl_xor_sync(0xffffffffu, p, o);
    __shared__ int wsum[8];
    __shared__ int s_off;
    if (lane == 0) wsum[wid] = p;
    __syncthreads();
    if (tid == 0) {
        int s = 0;
#pragma unroll
        for (int w = 0; w < 8; ++w) s += wsum[w];
        s_off = s;
    }
    __syncthreads();
    int i = blockIdx.x * 256 + tid;
    if (i < n) {
        int r = g_rowptr[i] + s_off;
        g_rowptr[i] = r;
        g_cursor[i] = r;
    }
    if (i == 0) g_rowptr[n] = E;
}

__global__ void scatter_kernel(const int* __restrict__ src, const int* __restrict__ dst, int E) {
    int q = blockIdx.x * blockDim.x + threadIdx.x;
    int e = q * 4;
    if (e + 4 <= E) {
        int4 s4 = *(const int4*)(src + e);
        int4 d4 = *(const int4*)(dst + e);
        g_csrc[atomicAdd(&g_cursor[d4.x], 1)] = s4.x;
        g_csrc[atomicAdd(&g_cursor[d4.y], 1)] = s4.y;
        g_csrc[atomicAdd(&g_cursor[d4.z], 1)] = s4.z;
        g_csrc[atomicAdd(&g_cursor[d4.w], 1)] = s4.w;
    } else {
        for (int i = e; i < E; ++i)
            g_csrc[atomicAdd(&g_cursor[dst[i]], 1)] = src[i];
    }
}

// ---------------- gather attention: fp16 K/V, warp per node ----------------
__device__ __forceinline__ float4 unp4(uint2 u) {
    float2 a = __half22float2(*reinterpret_cast<const __half2*>(&u.x));
    float2 b = __half22float2(*reinterpret_cast<const __half2*>(&u.y));
    return make_float4(a.x, a.y, b.x, b.y);
}

__global__ __launch_bounds__(256) void gather_kernel(int n) {
    int warp = (blockIdx.x * blockDim.x + threadIdx.x) >> 5;
    if (warp >= n) return;
    const int lid = threadIdx.x & 31;
    const int d = warp;
    const size_t base = (size_t)d * (D / 2) + lid * 2;

    float4 q = unp4(*(const uint2*)(g_Qh + base));
    float4 acc = make_float4(0.f, 0.f, 0.f, 0.f);
    float zacc = 0.f;

    int beg = g_rowptr[d], end = g_rowptr[d + 1];
    int i = beg;
    for (; i + 2 <= end; i += 2) {
        int s0 = g_csrc[i], s1 = g_csrc[i + 1];
        size_t o0 = (size_t)s0 * (D / 2) + lid * 2;
        size_t o1 = (size_t)s1 * (D / 2) + lid * 2;
        float4 k0 = unp4(*(const uint2*)(g_Kh + o0));
        float4 k1 = unp4(*(const uint2*)(g_Kh + o1));
        float4 v0 = unp4(*(const uint2*)(g_Vh + o0));
        float4 v1 = unp4(*(const uint2*)(g_Vh + o1));
        float p0 = q.x * k0.x + q.y * k0.y + q.z * k0.z + q.w * k0.w;
        float p1 = q.x * k1.x + q.y * k1.y + q.z * k1.z + q.w * k1.w;
        p0 += __shfl_xor_sync(0xffffffffu, p0, 1);
        p1 += __shfl_xor_sync(0xffffffffu, p1, 1);
        p0 += __shfl_xor_sync(0xffffffffu, p0, 2);
        p1 += __shfl_xor_sync(0xffffffffu, p1, 2);
        float sc0 = __expf(fminf(fmaxf(p0 * 0.25f, -5.f), 5.f));
        float sc1 = __expf(fminf(fmaxf(p1 * 0.25f, -5.f), 5.f));
        acc.x += v0.x * sc0 + v1.x * sc1;
        acc.y += v0.y * sc0 + v1.y * sc1;
        acc.z += v0.z * sc0 + v1.z * sc1;
        acc.w += v0.w * sc0 + v1.w * sc1;
        zacc += sc0 + sc1;
    }
    if (i < end) {
        int s0 = g_csrc[i];
        size_t o0 = (size_t)s0 * (D / 2) + lid * 2;
        float4 k0 = unp4(*(const uint2*)(g_Kh + o0));
        float4 v0 = unp4(*(const uint2*)(g_Vh + o0));
        float p0 = q.x * k0.x + q.y * k0.y + q.z * k0.z + q.w * k0.w;
        p0 += __shfl_xor_sync(0xffffffffu, p0, 1);
        p0 += __shfl_xor_sync(0xffffffffu, p0, 2);
        float sc0 = __expf(fminf(fmaxf(p0 * 0.25f, -5.f), 5.f));
        acc.x += v0.x * sc0; acc.y += v0.y * sc0;
        acc.z += v0.z * sc0; acc.w += v0.w * sc0;
        zacc += sc0;
    }
    float inv = 1.0f / zacc;
    *(uint2*)(g_attn + base) = make_uint2(pack_h2(acc.x * inv, acc.y * inv),
                                          pack_h2(acc.z * inv, acc.w * inv));
}

// ---------------- tensor-core GEMM: 128x128 tile, fp16, 2-stage pipeline --------
enum { EPI_STORE_H = 0, EPI_BIAS_RESID = 1, EPI_BIAS_RELU_H = 2 };

#define BK 64
#define SK 72
#define TILEB (128 * SK * 2)
#define STAGE_B (2 * TILEB)
#define DSMEM_BYTES (2 * STAGE_B)

template <int EPI, bool STATS, bool RESBN, int KT>
__device__ __forceinline__ void tgemm_core(
    const __half* __restrict__ A, const __half* __restrict__ W,
    const float* __restrict__ bias, const float* __restrict__ resid,
    const float* __restrict__ t0, const float* __restrict__ t1,
    float* __restrict__ ssum, float* __restrict__ ssq,
    float* __restrict__ Cf, uint32_t* __restrict__ Ch,
    int M, int ldc, int rowBase, int colBase)
{
    extern __shared__ __align__(16) char sm[];
    const uint32_t smbase = smem_u32(sm);

    const int tid = threadIdx.x;
    const int wid = tid >> 5;
    const int lid = tid & 31;
    const int warp_m = wid & 1;
    const int warp_n = wid >> 1;

    const int ar = (lid & 7) + ((lid >> 3) & 1) * 8;
    const int ac = (lid >> 4) * 8;
    const int br = lid & 7;
    const int bc = ((lid >> 3) & 1) * 8;

    const uint32_t aOff = (uint32_t)((warp_m * 64 + ar) * SK + ac) * 2;
    const uint32_t bOff = (uint32_t)((warp_n * 32 + br) * SK + bc) * 2;

    float acc[4][4][4];
#pragma unroll
    for (int i = 0; i < 4; ++i)
#pragma unroll
        for (int j = 0; j < 4; ++j)
#pragma unroll
            for (int t = 0; t < 4; ++t) acc[i][j][t] = 0.f;

    const int row = tid >> 1;
    const int kh = (tid & 1) * 32;
    const int grow = rowBase + row;
    const bool valid = grow < M;

    const __half* pA = A + (size_t)grow * KT + kh;
    const __half* pW = W + (size_t)(colBase + row) * KT + kh;
    const uint32_t sdst = (uint32_t)(row * SK + kh) * 2;

    auto load_slab = [&](int slab, int stage) {
        uint32_t sb = smbase + stage * STAGE_B + sdst;
        const __half* a = pA + slab * BK;
        const __half* w = pW + slab * BK;
#pragma unroll
        for (int c = 0; c < 4; ++c) cp16z(sb + c * 16, a + c * 8, valid);
#pragma unroll
        for (int c = 0; c < 4; ++c) cp16(sb + TILEB + c * 16, w + c * 8);
        CP_COMMIT();
    };

    constexpr int NSLAB = KT / BK;
    load_slab(0, 0);
#pragma unroll
    for (int s = 0; s < NSLAB; ++s) {
        if (s + 1 < NSLAB) {
            load_slab(s + 1, (s + 1) & 1);
            CP_WAIT1();
        } else {
            CP_WAIT0();
        }
        __syncthreads();

        const uint32_t stA = smbase + (s & 1) * STAGE_B;
        const uint32_t stW = stA + TILEB;
#pragma unroll
        for (int ks = 0; ks < 4; ++ks) {
            const uint32_t k0 = (uint32_t)(ks * 16) * 2;
            uint32_t bh[4][2];
#pragma unroll
            for (int j = 0; j < 4; ++j)
                ldm_x2(bh[j][0], bh[j][1], stW + bOff + (uint32_t)(j * 8 * SK) * 2 + k0);
#pragma unroll
            for (int i = 0; i < 4; ++i) {
                uint32_t a0, a1, a2, a3;
                ldm_x4(a0, a1, a2, a3, stA + aOff + (uint32_t)(i * 16 * SK) * 2 + k0);
#pragma unroll
                for (int j = 0; j < 4; ++j)
                    mma_f16(acc[i][j], a0, a1, a2, a3, bh[j][0], bh[j][1]);
            }
        }
        if (s + 1 < NSLAB) __syncthreads();
    }

    // ---- epilogue ----
    const int rr = lid >> 2;
    const int cc = (lid & 3) * 2;
    float cs[8], cq[8];
    if (STATS) {
#pragma unroll
        for (int t = 0; t < 8; ++t) { cs[t] = 0.f; cq[t] = 0.f; }
    }
#pragma unroll
    for (int i = 0; i < 4; ++i) {
#pragma unroll
        for (int hf = 0; hf < 2; ++hf) {
            int r = rowBase + warp_m * 64 + i * 16 + rr + hf * 8;
            if (r >= M) continue;
#pragma unroll
            for (int j = 0; j < 4; ++j) {
                int col = colBase + warp_n * 32 + j * 8 + cc;
                float v0 = acc[i][j][hf * 2];
                float v1 = acc[i][j][hf * 2 + 1];
                if (EPI == EPI_BIAS_RESID) {
                    v0 += bias[col];
                    v1 += bias[col + 1];
                    float r0 = resid[(size_t)r * D + col];
                    float r1 = resid[(size_t)r * D + col + 1];
                    if (RESBN) {
                        r0 = r0 * t0[col] + t1[col];
                        r1 = r1 * t0[col + 1] + t1[col + 1];
                    }
                    v0 += r0; v1 += r1;
                } else if (EPI == EPI_BIAS_RELU_H) {
                    v0 = fmaxf(v0 + bias[col], 0.f);
                    v1 = fmaxf(v1 + bias[col + 1], 0.f);
                }
                if (STATS) {
                    cs[j * 2] += v0;     cq[j * 2] += v0 * v0;
                    cs[j * 2 + 1] += v1; cq[j * 2 + 1] += v1 * v1;
                }
                if (EPI == EPI_BIAS_RESID) {
                    *(float2*)(Cf + (size_t)r * ldc + col) = make_float2(v0, v1);
                } else {
                    Ch[((size_t)r * ldc + col) >> 1] = pack_h2(v0, v1);
                }
            }
        }
    }
    if (STATS) {
#pragma unroll
        for (int t = 0; t < 8; ++t) {
#pragma unroll
            for (int o = 4; o < 32; o <<= 1) {
                cs[t] += __shfl_xor_sync(0xffffffffu, cs[t], o);
                cq[t] += __shfl_xor_sync(0xffffffffu, cq[t], o);
            }
        }
        if (lid < 4) {
#pragma unroll
            for (int t = 0; t < 8; ++t) {
                int col = colBase + warp_n * 32 + (t >> 1) * 8 + lid * 2 + (t & 1);
                atomicAdd(&ssum[col & (D - 1)], cs[t]);
                atomicAdd(&ssq[col & (D - 1)], cq[t]);
            }
        }
    }
}

template <int EPI, bool STATS, bool RESBN, int KT>
__global__ __launch_bounds__(256, 2) void tgemm_k(
    const __half* __restrict__ A, const __half* __restrict__ W,
    const float* __restrict__ bias, const float* __restrict__ resid,
    const float* __restrict__ t0, const float* __restrict__ t1,
    float* __restrict__ ssum, float* __restrict__ ssq,
    float* __restrict__ Cf, uint32_t* __restrict__ Ch, int M, int ldc)
{
    tgemm_core<EPI, STATS, RESBN, KT>(A, W, bias, resid, t0, t1, ssum, ssq, Cf, Ch,
                                      M, ldc, blockIdx.x * 128, blockIdx.y * 128);
}

__global__ __launch_bounds__(256, 2) void qkv_kernel(int M) {
    int off = (blockIdx.y == 0) ? OFF_WQ : (blockIdx.y == 1) ? OFF_WK : OFF_WV;
    uint32_t* C = (blockIdx.y == 0) ? g_Qh : (blockIdx.y == 1) ? g_Kh : g_Vh;
    tgemm_core<EPI_STORE_H, false, false, 128>(
        (const __half*)g_hh, g_w + off, nullptr, nullptr, nullptr, nullptr,
        nullptr, nullptr, nullptr, C, M, D, blockIdx.x * 128, 0);
}

// ---------------- BN1: fused finalize + convert ----------------
__global__ __launch_bounds__(256) void bn_convert(
    const float* __restrict__ x1, const float* __restrict__ sum, const float* __restrict__ sq,
    const float* __restrict__ g, const float* __restrict__ b,
    float* __restrict__ bn_out, int npair, int M)
{
    __shared__ float s_sc[D], s_sh[D];
    int tid = threadIdx.x;
    if (tid < D) {
        float invM = 1.0f / (float)M;
        float mu = sum[tid] * invM;
        float var = sq[tid] * invM - mu * mu;
        float sc = g[tid] * rsqrtf(var + 1e-5f);
        s_sc[tid] = sc;
        s_sh[tid] = b[tid] - mu * sc;
        if (blockIdx.x == 0) {
            bn_out[tid] = sc;
            bn_out[D + tid] = s_sh[tid];
        }
    }
    __syncthreads();
    int p = blockIdx.x * blockDim.x + tid;
    if (p >= npair) return;
    float2 v = ((const float2*)x1)[p];
    int col = (p * 2) & (D - 1);
    g_bx1[p] = pack_h2(v.x * s_sc[col] + s_sh[col], v.y * s_sc[col + 1] + s_sh[col + 1]);
}

// bn_apply with inline BN2 finalize + float4 I/O
__global__ __launch_bounds__(256) void bn_apply(
    const float* __restrict__ x, const float* __restrict__ sum, const float* __restrict__ sq,
    const float* __restrict__ g, const float* __restrict__ b,
    float* __restrict__ out, int M)
{
    __shared__ float s_sc[D], s_sh[D];
    int tid = threadIdx.x;
    if (tid < D) {
        float invM = 1.0f / (float)M;
        float mu = sum[tid] * invM;
        float var = sq[tid] * invM - mu * mu;
        float sc = g[tid] * rsqrtf(var + 1e-5f);
        s_sc[tid] = sc;
        s_sh[tid] = b[tid] - mu * sc;
    }
    __syncthreads();
    int total4 = M * D / 4;
    int stride = gridDim.x * blockDim.x;
    for (int i = blockIdx.x * blockDim.x + tid; i < total4; i += stride) {
        float4 v = ((const float4*)x)[i];
        int col = (i * 4) & (D - 1);
        v.x = v.x * s_sc[col] + s_sh[col];
        v.y = v.y * s_sc[col + 1] + s_sh[col + 1];
        v.z = v.z * s_sc[col + 2] + s_sh[col + 2];
        v.w = v.w * s_sc[col + 3] + s_sh[col + 3];
        ((float4*)out)[i] = v;
    }
}

// ---------------- host launch ----------------
extern "C" void kernel_launch(void* const* d_in, const int* in_sizes, int n_in,
                              void* d_out, int out_size)
{
    const float* h    = (const float*)d_in[0];
    const int*   src  = (const int*)d_in[1];
    const int*   dst  = (const int*)d_in[2];
    const float* WQ   = (const float*)d_in[3];
    const float* WK   = (const float*)d_in[4];
    const float* WV   = (const float*)d_in[5];
    const float* WO   = (const float*)d_in[6];
    const float* bO   = (const float*)d_in[7];
    const float* W1   = (const float*)d_in[8];
    const float* b1   = (const float*)d_in[9];
    const float* W2   = (const float*)d_in[10];
    const float* b2   = (const float*)d_in[11];
    const float* bn1g = (const float*)d_in[12];
    const float* bn1b = (const float*)d_in[13];
    const float* bn2g = (const float*)d_in[14];
    const float* bn2b = (const float*)d_in[15];
    float* out = (float*)d_out;

    int M = in_sizes[0] / D;
    int E = in_sizes[1];
    if (M > N_NODES) M = N_NODES;
    if (E > N_EDGES) E = N_EDGES;

    float *x1p, *x2p, *stp, *bn1p;
    uint32_t *attnp, *bx1p, *midp;
    __half *wp;
    cudaGetSymbolAddress((void**)&x1p, g_x1);
    cudaGetSymbolAddress((void**)&x2p, g_x2);
    cudaGetSymbolAddress((void**)&stp, g_stats);
    cudaGetSymbolAddress((void**)&bn1p, g_bn1);
    cudaGetSymbolAddress((void**)&attnp, g_attn);
    cudaGetSymbolAddress((void**)&bx1p, g_bx1);
    cudaGetSymbolAddress((void**)&midp, g_midh);
    cudaGetSymbolAddress((void**)&wp, g_w);

    cudaFuncSetAttribute(qkv_kernel, cudaFuncAttributeMaxDynamicSharedMemorySize, DSMEM_BYTES);
    cudaFuncSetAttribute(tgemm_k<EPI_BIAS_RESID, true, false, 128>,
                         cudaFuncAttributeMaxDynamicSharedMemorySize, DSMEM_BYTES);
    cudaFuncSetAttribute(tgemm_k<EPI_BIAS_RELU_H, false, false, 128>,
                         cudaFuncAttributeMaxDynamicSharedMemorySize, DSMEM_BYTES);
    cudaFuncSetAttribute(tgemm_k<EPI_BIAS_RESID, true, true, 256>,
                         cudaFuncAttributeMaxDynamicSharedMemorySize, DSMEM_BYTES);

    dim3 blk(256);
    int gx = (M + 127) / 128;
    int nb = (M + 255) / 256;
    int npair = M * D / 2;
    int cvb = (npair + 255) / 256;
    int e4 = (E + 3) / 4;

    prep_kernel<<<cvb, 256>>>(h, WQ, WK, WV, WO, W1, W2, npair);

    hist_kernel<<<(e4 + 255) / 256, 256>>>(dst, E);
    scan_local<<<nb, 256>>>(M);
    scan_final<<<nb, 256>>>(M, E);
    scatter_kernel<<<(e4 + 255) / 256, 256>>>(src, dst, E);

    qkv_kernel<<<dim3(gx, 3), blk, DSMEM_BYTES>>>(M);

    gather_kernel<<<(M * 32 + 255) / 256, 256>>>(M);

    tgemm_k<EPI_BIAS_RESID, true, false, 128><<<dim3(gx, 1), blk, DSMEM_BYTES>>>(
        (const __half*)attnp, wp + OFF_WO, bO, h, nullptr, nullptr,
        stp, stp + D, x1p, nullptr, M, D);

    bn_convert<<<cvb, 256>>>(x1p, stp, stp + D, bn1g, bn1b, bn1p, npair, M);

    tgemm_k<EPI_BIAS_RELU_H, false, false, 128><<<dim3(gx, 2), blk, DSMEM_BYTES>>>(
        (const __half*)bx1p, wp + OFF_W1, b1, nullptr, nullptr, nullptr,
        nullptr, nullptr, nullptr, midp, M, 2 * D);

    tgemm_k<EPI_BIAS_RESID, true, true, 256><<<dim3(gx, 1), blk, DSMEM_BYTES>>>(
        (const __half*)midp, wp + OFF_W2, b2, x1p, bn1p, bn1p + D,
        stp + 2 * D, stp + 3 * D, x2p, nullptr, M, D);

    bn_apply<<<1024, 256>>>(x2p, stp + 2 * D, stp + 3 * D, bn2g, bn2b, out, M);
}

// round 14
// speedup vs baseline: 1.5839x; 1.0061x over previous
#include <cuda_runtime.h>
#include <cuda_fp16.h>
#include <math.h>
#include <stdint.h>

#define N_NODES 50000
#define N_EDGES 640000
#define D 128
#define H 8

// ---------------- scratch (static device globals; no allocation) ----------------
__device__ float g_x1[N_NODES * D];
__device__ float g_x2[N_NODES * D];
__device__ float g_stats[4 * D];
__device__ float g_bn1[2 * D];
// fp16x2-packed buffers
__device__ uint32_t g_Qh [N_NODES * D / 2];
__device__ uint32_t g_Kh [N_NODES * D / 2];
__device__ uint32_t g_Vh [N_NODES * D / 2];
__device__ uint32_t g_attn[N_NODES * D / 2];
__device__ uint32_t g_hh [N_NODES * D / 2];
__device__ uint32_t g_bx1[N_NODES * D / 2];
__device__ uint32_t g_midh[N_NODES * D];
// CSR
__device__ int g_rowptr[N_NODES + 1];
__device__ int g_cursor[N_NODES];
__device__ int g_csrc[N_EDGES];
__device__ int g_part[256];
// pre-converted weights (fp16)
#define W_TOTAL 131072
__device__ __half g_w[W_TOTAL];
#define OFF_WQ 0
#define OFF_WK 16384
#define OFF_WV 32768
#define OFF_WO 49152
#define OFF_W1 65536
#define OFF_W2 98304

// ---------------- helpers ----------------
__device__ __forceinline__ uint32_t smem_u32(const void* p) {
    uint32_t a;
    asm("{ .reg .u64 t; cvta.to.shared.u64 t, %1; cvt.u32.u64 %0, t; }" : "=r"(a) : "l"(p));
    return a;
}
__device__ __forceinline__ void ldm_x4(uint32_t& a0, uint32_t& a1, uint32_t& a2, uint32_t& a3,
                                       uint32_t addr) {
    asm volatile("ldmatrix.sync.aligned.m8n8.x4.shared.b16 {%0,%1,%2,%3}, [%4];"
                 : "=r"(a0), "=r"(a1), "=r"(a2), "=r"(a3) : "r"(addr));
}
__device__ __forceinline__ void ldm_x2(uint32_t& b0, uint32_t& b1, uint32_t addr) {
    asm volatile("ldmatrix.sync.aligned.m8n8.x2.shared.b16 {%0,%1}, [%2];"
                 : "=r"(b0), "=r"(b1) : "r"(addr));
}
__device__ __forceinline__ void mma_f16(float* c, uint32_t a0, uint32_t a1, uint32_t a2,
                                        uint32_t a3, uint32_t b0, uint32_t b1) {
    asm volatile(
        "mma.sync.aligned.m16n8k16.row.col.f32.f16.f16.f32 "
        "{%0,%1,%2,%3}, {%4,%5,%6,%7}, {%8,%9}, {%0,%1,%2,%3};"
        : "+f"(c[0]), "+f"(c[1]), "+f"(c[2]), "+f"(c[3])
        : "r"(a0), "r"(a1), "r"(a2), "r"(a3), "r"(b0), "r"(b1));
}
__device__ __forceinline__ uint32_t pack_h2(float a, float b) {
    uint32_t r;
    asm("cvt.rn.f16x2.f32 %0, %1, %2;" : "=r"(r) : "f"(b), "f"(a));
    return r;
}
__device__ __forceinline__ void cp16(uint32_t dst, const void* src) {
    asm volatile("cp.async.cg.shared.global [%0], [%1], 16;" :: "r"(dst), "l"(src));
}
__device__ __forceinline__ void cp16z(uint32_t dst, const void* src, bool pred) {
    int sz = pred ? 16 : 0;
    asm volatile("cp.async.cg.shared.global [%0], [%1], 16, %2;"
                 :: "r"(dst), "l"(src), "r"(sz));
}
#define CP_COMMIT() asm volatile("cp.async.commit_group;" ::: "memory")
#define CP_WAIT0()  asm volatile("cp.async.wait_group 0;" ::: "memory")
#define CP_WAIT1()  asm volatile("cp.async.wait_group 1;" ::: "memory")

// ---------------- fused prep: stats zero + weight convert + h convert ----------
__global__ void prep_kernel(const float* __restrict__ h,
                            const float* __restrict__ WQ, const float* __restrict__ WK,
                            const float* __restrict__ WV, const float* __restrict__ WO,
                            const float* __restrict__ W1, const float* __restrict__ W2,
                            int npair)
{
    int gid = blockIdx.x * blockDim.x + threadIdx.x;
    if (gid < npair) {
        float2 v = ((const float2*)h)[gid];
        g_hh[gid] = pack_h2(v.x, v.y);
    }
    if (gid < W_TOTAL / 2) {
        int elem = gid * 2;
        const float* src;
        int local;
        if (elem < OFF_W1) {
            int m = elem >> 14;
            local = elem & 16383;
            src = (m == 0) ? WQ : (m == 1) ? WK : (m == 2) ? WV : WO;
        } else if (elem < OFF_W2) {
            local = elem - OFF_W1;
            src = W1;
        } else {
            local = elem - OFF_W2;
            src = W2;
        }
        ((uint32_t*)g_w)[gid] = pack_h2(src[local], src[local + 1]);
    }
    if (gid < 4 * D) g_stats[gid] = 0.f;
}

// ---------------- CSR build (side stream) ----------------
__global__ void zero_cursor(int n) {
    int i = blockIdx.x * blockDim.x + threadIdx.x;
    if (i < n) g_cursor[i] = 0;
}

__global__ void hist_kernel(const int* __restrict__ dst, int E) {
    int q = blockIdx.x * blockDim.x + threadIdx.x;
    int e = q * 4;
    if (e + 4 <= E) {
        int4 d4 = *(const int4*)(dst + e);
        atomicAdd(&g_cursor[d4.x], 1);
        atomicAdd(&g_cursor[d4.y], 1);
        atomicAdd(&g_cursor[d4.z], 1);
        atomicAdd(&g_cursor[d4.w], 1);
    } else {
        for (int i = e; i < E; ++i) atomicAdd(&g_cursor[dst[i]], 1);
    }
}

__global__ __launch_bounds__(256) void scan_local(int n) {
    int tid = threadIdx.x;
    int lane = tid & 31;
    int wid = tid >> 5;
    int i = blockIdx.x * 256 + tid;
    int c = (i < n) ? g_cursor[i] : 0;
    int v = c;
#pragma unroll
    for (int o = 1; o < 32; o <<= 1) {
        int t = __shfl_up_sync(0xffffffffu, v, o);
        if (lane >= o) v += t;
    }
    __shared__ int wsum[8];
    if (lane == 31) wsum[wid] = v;
    __syncthreads();
    if (wid == 0 && lane < 8) {
        int w = wsum[lane];
#pragma unroll
        for (int o = 1; o < 8; o <<= 1) {
            int t = __shfl_up_sync(0xffu, w, o);
            if (lane >= o) w += t;
        }
        wsum[lane] = w;
    }
    __syncthreads();
    int off = (wid > 0) ? wsum[wid - 1] : 0;
    if (i < n) g_rowptr[i] = v - c + off;
    if (tid == 255) g_part[blockIdx.x] = v + off;
}

__global__ __launch_bounds__(256) void scan_final(int n, int E) {
    int tid = threadIdx.x;
    int lane = tid & 31;
    int wid = tid >> 5;
    int nb = gridDim.x;
    int p = (tid < nb && tid < (int)blockIdx.x) ? g_part[tid] : 0;
#pragma unroll
    for (int o = 16; o > 0; o >>= 1) p += __shfl_xor_sync(0xffffffffu, p, o);
    __shared__ int wsum[8];
    __shared__ int s_off;
    if (lane == 0) wsum[wid] = p;
    __syncthreads();
    if (tid == 0) {
        int s = 0;
#pragma unroll
        for (int w = 0; w < 8; ++w) s += wsum[w];
        s_off = s;
    }
    __syncthreads();
    int i = blockIdx.x * 256 + tid;
    if (i < n) {
        int r = g_rowptr[i] + s_off;
        g_rowptr[i] = r;
        g_cursor[i] = r;
    }
    if (i == 0) g_rowptr[n] = E;
}

__global__ void scatter_kernel(const int* __restrict__ src, const int* __restrict__ dst, int E) {
    int q = blockIdx.x * blockDim.x + threadIdx.x;
    int e = q * 4;
    if (e + 4 <= E) {
        int4 s4 = *(const int4*)(src + e);
        int4 d4 = *(const int4*)(dst + e);
        g_csrc[atomicAdd(&g_cursor[d4.x], 1)] = s4.x;
        g_csrc[atomicAdd(&g_cursor[d4.y], 1)] = s4.y;
        g_csrc[atomicAdd(&g_cursor[d4.z], 1)] = s4.z;
        g_csrc[atomicAdd(&g_cursor[d4.w], 1)] = s4.w;
    } else {
        for (int i = e; i < E; ++i)
            g_csrc[atomicAdd(&g_cursor[dst[i]], 1)] = src[i];
    }
}

// ---------------- gather attention: fp16 K/V, warp per node ----------------
__device__ __forceinline__ float4 unp4(uint2 u) {
    float2 a = __half22float2(*reinterpret_cast<const __half2*>(&u.x));
    float2 b = __half22float2(*reinterpret_cast<const __half2*>(&u.y));
    return make_float4(a.x, a.y, b.x, b.y);
}

__global__ __launch_bounds__(256) void gather_kernel(int n) {
    int warp = (blockIdx.x * blockDim.x + threadIdx.x) >> 5;
    if (warp >= n) return;
    const int lid = threadIdx.x & 31;
    const int d = warp;
    const size_t base = (size_t)d * (D / 2) + lid * 2;

    float4 q = unp4(*(const uint2*)(g_Qh + base));
    float4 acc = make_float4(0.f, 0.f, 0.f, 0.f);
    float zacc = 0.f;

    int beg = g_rowptr[d], end = g_rowptr[d + 1];
    int i = beg;
    for (; i + 2 <= end; i += 2) {
        int s0 = g_csrc[i], s1 = g_csrc[i + 1];
        size_t o0 = (size_t)s0 * (D / 2) + lid * 2;
        size_t o1 = (size_t)s1 * (D / 2) + lid * 2;
        float4 k0 = unp4(*(const uint2*)(g_Kh + o0));
        float4 k1 = unp4(*(const uint2*)(g_Kh + o1));
        float4 v0 = unp4(*(const uint2*)(g_Vh + o0));
        float4 v1 = unp4(*(const uint2*)(g_Vh + o1));
        float p0 = q.x * k0.x + q.y * k0.y + q.z * k0.z + q.w * k0.w;
        float p1 = q.x * k1.x + q.y * k1.y + q.z * k1.z + q.w * k1.w;
        p0 += __shfl_xor_sync(0xffffffffu, p0, 1);
        p1 += __shfl_xor_sync(0xffffffffu, p1, 1);
        p0 += __shfl_xor_sync(0xffffffffu, p0, 2);
        p1 += __shfl_xor_sync(0xffffffffu, p1, 2);
        float sc0 = __expf(fminf(fmaxf(p0 * 0.25f, -5.f), 5.f));
        float sc1 = __expf(fminf(fmaxf(p1 * 0.25f, -5.f), 5.f));
        acc.x += v0.x * sc0 + v1.x * sc1;
        acc.y += v0.y * sc0 + v1.y * sc1;
        acc.z += v0.z * sc0 + v1.z * sc1;
        acc.w += v0.w * sc0 + v1.w * sc1;
        zacc += sc0 + sc1;
    }
    if (i < end) {
        int s0 = g_csrc[i];
        size_t o0 = (size_t)s0 * (D / 2) + lid * 2;
        float4 k0 = unp4(*(const uint2*)(g_Kh + o0));
        float4 v0 = unp4(*(const uint2*)(g_Vh + o0));
        float p0 = q.x * k0.x + q.y * k0.y + q.z * k0.z + q.w * k0.w;
        p0 += __shfl_xor_sync(0xffffffffu, p0, 1);
        p0 += __shfl_xor_sync(0xffffffffu, p0, 2);
        float sc0 = __expf(fminf(fmaxf(p0 * 0.25f, -5.f), 5.f));
        acc.x += v0.x * sc0; acc.y += v0.y * sc0;
        acc.z += v0.z * sc0; acc.w += v0.w * sc0;
        zacc += sc0;
    }
    float inv = 1.0f / zacc;
    *(uint2*)(g_attn + base) = make_uint2(pack_h2(acc.x * inv, acc.y * inv),
                                          pack_h2(acc.z * inv, acc.w * inv));
}

// ---------------- tensor-core GEMM: 128x128 tile, fp16, 2-stage pipeline --------
enum { EPI_STORE_H = 0, EPI_BIAS_RESID = 1, EPI_BIAS_RELU_H = 2 };

#define BK 64
#define SK 72
#define TILEB (128 * SK * 2)
#define STAGE_B (2 * TILEB)
#define DSMEM_BYTES (2 * STAGE_B)

template <int EPI, bool STATS, bool RESBN, int KT>
__device__ __forceinline__ void tgemm_core(
    const __half* __restrict__ A, const __half* __restrict__ W,
    const float* __restrict__ bias, const float* __restrict__ resid,
    const float* __restrict__ t0, const float* __restrict__ t1,
    float* __restrict__ ssum, float* __restrict__ ssq,
    float* __restrict__ Cf, uint32_t* __restrict__ Ch,
    int M, int ldc, int rowBase, int colBase)
{
    extern __shared__ __align__(16) char sm[];
    const uint32_t smbase = smem_u32(sm);

    const int tid = threadIdx.x;
    const int wid = tid >> 5;
    const int lid = tid & 31;
    const int warp_m = wid & 1;
    const int warp_n = wid >> 1;

    const int ar = (lid & 7) + ((lid >> 3) & 1) * 8;
    const int ac = (lid >> 4) * 8;
    const int br = lid & 7;
    const int bc = ((lid >> 3) & 1) * 8;

    const uint32_t aOff = (uint32_t)((warp_m * 64 + ar) * SK + ac) * 2;
    const uint32_t bOff = (uint32_t)((warp_n * 32 + br) * SK + bc) * 2;

    float acc[4][4][4];
#pragma unroll
    for (int i = 0; i < 4; ++i)
#pragma unroll
        for (int j = 0; j < 4; ++j)
#pragma unroll
            for (int t = 0; t < 4; ++t) acc[i][j][t] = 0.f;

    const int row = tid >> 1;
    const int kh = (tid & 1) * 32;
    const int grow = rowBase + row;
    const bool valid = grow < M;

    const __half* pA = A + (size_t)grow * KT + kh;
    const __half* pW = W + (size_t)(colBase + row) * KT + kh;
    const uint32_t sdst = (uint32_t)(row * SK + kh) * 2;

    auto load_slab = [&](int slab, int stage) {
        uint32_t sb = smbase + stage * STAGE_B + sdst;
        const __half* a = pA + slab * BK;
        const __half* w = pW + slab * BK;
#pragma unroll
        for (int c = 0; c < 4; ++c) cp16z(sb + c * 16, a + c * 8, valid);
#pragma unroll
        for (int c = 0; c < 4; ++c) cp16(sb + TILEB + c * 16, w + c * 8);
        CP_COMMIT();
    };

    constexpr int NSLAB = KT / BK;
    load_slab(0, 0);
#pragma unroll
    for (int s = 0; s < NSLAB; ++s) {
        if (s + 1 < NSLAB) {
            load_slab(s + 1, (s + 1) & 1);
            CP_WAIT1();
        } else {
            CP_WAIT0();
        }
        __syncthreads();

        const uint32_t stA = smbase + (s & 1) * STAGE_B;
        const uint32_t stW = stA + TILEB;
#pragma unroll
        for (int ks = 0; ks < 4; ++ks) {
            const uint32_t k0 = (uint32_t)(ks * 16) * 2;
            uint32_t bh[4][2];
#pragma unroll
            for (int j = 0; j < 4; ++j)
                ldm_x2(bh[j][0], bh[j][1], stW + bOff + (uint32_t)(j * 8 * SK) * 2 + k0);
#pragma unroll
            for (int i = 0; i < 4; ++i) {
                uint32_t a0, a1, a2, a3;
                ldm_x4(a0, a1, a2, a3, stA + aOff + (uint32_t)(i * 16 * SK) * 2 + k0);
#pragma unroll
                for (int j = 0; j < 4; ++j)
                    mma_f16(acc[i][j], a0, a1, a2, a3, bh[j][0], bh[j][1]);
            }
        }
        // trailing sync only needed before the NEXT prefetch overwrites a live buffer
        if (s + 2 < NSLAB) __syncthreads();
    }

    // ---- epilogue ----
    const int rr = lid >> 2;
    const int cc = (lid & 3) * 2;
    float cs[8], cq[8];
    if (STATS) {
#pragma unroll
        for (int t = 0; t < 8; ++t) { cs[t] = 0.f; cq[t] = 0.f; }
    }
#pragma unroll
    for (int i = 0; i < 4; ++i) {
#pragma unroll
        for (int hf = 0; hf < 2; ++hf) {
            int r = rowBase + warp_m * 64 + i * 16 + rr + hf * 8;
            if (r >= M) continue;
#pragma unroll
            for (int j = 0; j < 4; ++j) {
                int col = colBase + warp_n * 32 + j * 8 + cc;
                float v0 = acc[i][j][hf * 2];
                float v1 = acc[i][j][hf * 2 + 1];
                if (EPI == EPI_BIAS_RESID) {
                    v0 += bias[col];
                    v1 += bias[col + 1];
                    float r0 = resid[(size_t)r * D + col];
                    float r1 = resid[(size_t)r * D + col + 1];
                    if (RESBN) {
                        r0 = r0 * t0[col] + t1[col];
                        r1 = r1 * t0[col + 1] + t1[col + 1];
                    }
                    v0 += r0; v1 += r1;
                } else if (EPI == EPI_BIAS_RELU_H) {
                    v0 = fmaxf(v0 + bias[col], 0.f);
                    v1 = fmaxf(v1 + bias[col + 1], 0.f);
                }
                if (STATS) {
                    cs[j * 2] += v0;     cq[j * 2] += v0 * v0;
                    cs[j * 2 + 1] += v1; cq[j * 2 + 1] += v1 * v1;
                }
                if (EPI == EPI_BIAS_RESID) {
                    *(float2*)(Cf + (size_t)r * ldc + col) = make_float2(v0, v1);
                } else {
                    Ch[((size_t)r * ldc + col) >> 1] = pack_h2(v0, v1);
                }
            }
        }
    }
    if (STATS) {
#pragma unroll
        for (int t = 0; t < 8; ++t) {
#pragma unroll
            for (int o = 4; o < 32; o <<= 1) {
                cs[t] += __shfl_xor_sync(0xffffffffu, cs[t], o);
                cq[t] += __shfl_xor_sync(0xffffffffu, cq[t], o);
            }
        }
        if (lid < 4) {
#pragma unroll
            for (int t = 0; t < 8; ++t) {
                int col = colBase + warp_n * 32 + (t >> 1) * 8 + lid * 2 + (t & 1);
                atomicAdd(&ssum[col & (D - 1)], cs[t]);
                atomicAdd(&ssq[col & (D - 1)], cq[t]);
            }
        }
    }
}

template <int EPI, bool STATS, bool RESBN, int KT>
__global__ __launch_bounds__(256, 2) void tgemm_k(
    const __half* __restrict__ A, const __half* __restrict__ W,
    const float* __restrict__ bias, const float* __restrict__ resid,
    const float* __restrict__ t0, const float* __restrict__ t1,
    float* __restrict__ ssum, float* __restrict__ ssq,
    float* __restrict__ Cf, uint32_t* __restrict__ Ch, int M, int ldc)
{
    tgemm_core<EPI, STATS, RESBN, KT>(A, W, bias, resid, t0, t1, ssum, ssq, Cf, Ch,
                                      M, ldc, blockIdx.x * 128, blockIdx.y * 128);
}

__global__ __launch_bounds__(256, 2) void qkv_kernel(int M) {
    int off = (blockIdx.y == 0) ? OFF_WQ : (blockIdx.y == 1) ? OFF_WK : OFF_WV;
    uint32_t* C = (blockIdx.y == 0) ? g_Qh : (blockIdx.y == 1) ? g_Kh : g_Vh;
    tgemm_core<EPI_STORE_H, false, false, 128>(
        (const __half*)g_hh, g_w + off, nullptr, nullptr, nullptr, nullptr,
        nullptr, nullptr, nullptr, C, M, D, blockIdx.x * 128, 0);
}

// ---------------- BN1: fused finalize + convert ----------------
__global__ __launch_bounds__(256) void bn_convert(
    const float* __restrict__ x1, const float* __restrict__ sum, const float* __restrict__ sq,
    const float* __restrict__ g, const float* __restrict__ b,
    float* __restrict__ bn_out, int npair, int M)
{
    __shared__ float s_sc[D], s_sh[D];
    int tid = threadIdx.x;
    if (tid < D) {
        float invM = 1.0f / (float)M;
        float mu = sum[tid] * invM;
        float var = sq[tid] * invM - mu * mu;
        float sc = g[tid] * rsqrtf(var + 1e-5f);
        s_sc[tid] = sc;
        s_sh[tid] = b[tid] - mu * sc;
        if (blockIdx.x == 0) {
            bn_out[tid] = sc;
            bn_out[D + tid] = s_sh[tid];
        }
    }
    __syncthreads();
    int p = blockIdx.x * blockDim.x + tid;
    if (p >= npair) return;
    float2 v = ((const float2*)x1)[p];
    int col = (p * 2) & (D - 1);
    g_bx1[p] = pack_h2(v.x * s_sc[col] + s_sh[col], v.y * s_sc[col + 1] + s_sh[col + 1]);
}

// bn_apply with inline BN2 finalize + float4 I/O
__global__ __launch_bounds__(256) void bn_apply(
    const float* __restrict__ x, const float* __restrict__ sum, const float* __restrict__ sq,
    const float* __restrict__ g, const float* __restrict__ b,
    float* __restrict__ out, int M)
{
    __shared__ float s_sc[D], s_sh[D];
    int tid = threadIdx.x;
    if (tid < D) {
        float invM = 1.0f / (float)M;
        float mu = sum[tid] * invM;
        float var = sq[tid] * invM - mu * mu;
        float sc = g[tid] * rsqrtf(var + 1e-5f);
        s_sc[tid] = sc;
        s_sh[tid] = b[tid] - mu * sc;
    }
    __syncthreads();
    int total4 = M * D / 4;
    int stride = gridDim.x * blockDim.x;
    for (int i = blockIdx.x * blockDim.x + tid; i < total4; i += stride) {
        float4 v = ((const float4*)x)[i];
        int col = (i * 4) & (D - 1);
        v.x = v.x * s_sc[col] + s_sh[col];
        v.y = v.y * s_sc[col + 1] + s_sh[col + 1];
        v.z = v.z * s_sc[col + 2] + s_sh[col + 2];
        v.w = v.w * s_sc[col + 3] + s_sh[col + 3];
        ((float4*)out)[i] = v;
    }
}

// ---------------- host launch ----------------
static cudaStream_t g_s1 = nullptr;
static cudaEvent_t g_e0 = nullptr, g_e1 = nullptr;

extern "C" void kernel_launch(void* const* d_in, const int* in_sizes, int n_in,
                              void* d_out, int out_size)
{
    const float* h    = (const float*)d_in[0];
    const int*   src  = (const int*)d_in[1];
    const int*   dst  = (const int*)d_in[2];
    const float* WQ   = (const float*)d_in[3];
    const float* WK   = (const float*)d_in[4];
    const float* WV   = (const float*)d_in[5];
    const float* WO   = (const float*)d_in[6];
    const float* bO   = (const float*)d_in[7];
    const float* W1   = (const float*)d_in[8];
    const float* b1   = (const float*)d_in[9];
    const float* W2   = (const float*)d_in[10];
    const float* b2   = (const float*)d_in[11];
    const float* bn1g = (const float*)d_in[12];
    const float* bn1b = (const float*)d_in[13];
    const float* bn2g = (const float*)d_in[14];
    const float* bn2b = (const float*)d_in[15];
    float* out = (float*)d_out;

    int M = in_sizes[0] / D;
    int E = in_sizes[1];
    if (M > N_NODES) M = N_NODES;
    if (E > N_EDGES) E = N_EDGES;

    float *x1p, *x2p, *stp, *bn1p;
    uint32_t *attnp, *bx1p, *midp;
    __half *wp;
    cudaGetSymbolAddress((void**)&x1p, g_x1);
    cudaGetSymbolAddress((void**)&x2p, g_x2);
    cudaGetSymbolAddress((void**)&stp, g_stats);
    cudaGetSymbolAddress((void**)&bn1p, g_bn1);
    cudaGetSymbolAddress((void**)&attnp, g_attn);
    cudaGetSymbolAddress((void**)&bx1p, g_bx1);
    cudaGetSymbolAddress((void**)&midp, g_midh);
    cudaGetSymbolAddress((void**)&wp, g_w);

    cudaFuncSetAttribute(qkv_kernel, cudaFuncAttributeMaxDynamicSharedMemorySize, DSMEM_BYTES);
    cudaFuncSetAttribute(tgemm_k<EPI_BIAS_RESID, true, false, 128>,
                         cudaFuncAttributeMaxDynamicSharedMemorySize, DSMEM_BYTES);
    cudaFuncSetAttribute(tgemm_k<EPI_BIAS_RELU_H, false, false, 128>,
                         cudaFuncAttributeMaxDynamicSharedMemorySize, DSMEM_BYTES);
    cudaFuncSetAttribute(tgemm_k<EPI_BIAS_RESID, true, true, 256>,
                         cudaFuncAttributeMaxDynamicSharedMemorySize, DSMEM_BYTES);

    // one-time side stream + events (host-side resources; no device allocation)
    if (g_s1 == nullptr) {
        if (cudaStreamCreateWithFlags(&g_s1, cudaStreamNonBlocking) != cudaSuccess)
            g_s1 = nullptr;
        cudaEventCreateWithFlags(&g_e0, cudaEventDisableTiming);
        cudaEventCreateWithFlags(&g_e1, cudaEventDisableTiming);
    }
    cudaStream_t s1 = g_s1 ? g_s1 : (cudaStream_t)0;

    dim3 blk(256);
    int gx = (M + 127) / 128;
    int nb = (M + 255) / 256;
    int npair = M * D / 2;
    int cvb = (npair + 255) / 256;
    int e4 = (E + 3) / 4;

    // fork: CSR chain on side stream, overlapped with prep + QKV on main stream
    cudaEventRecord(g_e0, 0);
    cudaStreamWaitEvent(s1, g_e0, 0);

    zero_cursor<<<nb, 256, 0, s1>>>(M);
    hist_kernel<<<(e4 + 255) / 256, 256, 0, s1>>>(dst, E);
    scan_local<<<nb, 256, 0, s1>>>(M);
    scan_final<<<nb, 256, 0, s1>>>(M, E);
    scatter_kernel<<<(e4 + 255) / 256, 256, 0, s1>>>(src, dst, E);
    cudaEventRecord(g_e1, s1);

    prep_kernel<<<cvb, 256>>>(h, WQ, WK, WV, WO, W1, W2, npair);
    qkv_kernel<<<dim3(gx, 3), blk, DSMEM_BYTES>>>(M);

    // join: gather needs both QKV (main) and CSR (side)
    cudaStreamWaitEvent(0, g_e1, 0);

    gather_kernel<<<(M * 32 + 255) / 256, 256>>>(M);

    tgemm_k<EPI_BIAS_RESID, true, false, 128><<<dim3(gx, 1), blk, DSMEM_BYTES>>>(
        (const __half*)attnp, wp + OFF_WO, bO, h, nullptr, nullptr,
        stp, stp + D, x1p, nullptr, M, D);

    bn_convert<<<cvb, 256>>>(x1p, stp, stp + D, bn1g, bn1b, bn1p, npair, M);

    tgemm_k<EPI_BIAS_RELU_H, false, false, 128><<<dim3(gx, 2), blk, DSMEM_BYTES>>>(
        (const __half*)bx1p, wp + OFF_W1, b1, nullptr, nullptr, nullptr,
        nullptr, nullptr, nullptr, midp, M, 2 * D);

    tgemm_k<EPI_BIAS_RESID, true, true, 256><<<dim3(gx, 1), blk, DSMEM_BYTES>>>(
        (const __half*)midp, wp + OFF_W2, b2, x1p, bn1p, bn1p + D,
        stp + 2 * D, stp + 3 * D, x2p, nullptr, M, D);

    bn_apply<<<1024, 256>>>(x2p, stp + 2 * D, stp + 3 * D, bn2g, bn2b, out, M);
}

// round 15
// speedup vs baseline: 1.5915x; 1.0048x over previous
#include <cuda_runtime.h>
#include <cuda_fp16.h>
#include <math.h>
#include <stdint.h>

#define N_NODES 50000
#define N_EDGES 640000
#define D 128
#define H 8

// ---------------- scratch (static device globals; no allocation) ----------------
__device__ float g_x2[N_NODES * D];
__device__ float g_stats[4 * D];
__device__ float g_bn1[2 * D];
// fp16x2-packed buffers
__device__ uint32_t g_Qh [N_NODES * D / 2];
__device__ uint32_t g_Kh [N_NODES * D / 2];
__device__ uint32_t g_Vh [N_NODES * D / 2];
__device__ uint32_t g_attn[N_NODES * D / 2];
__device__ uint32_t g_hh [N_NODES * D / 2];
__device__ uint32_t g_x1h[N_NODES * D / 2];   // x1 stored fp16
__device__ uint32_t g_bx1[N_NODES * D / 2];   // BN1(x1) fp16
__device__ uint32_t g_midh[N_NODES * D];
// CSR
__device__ int g_rowptr[N_NODES + 1];
__device__ int g_cursor[N_NODES];
__device__ int g_csrc[N_EDGES];
__device__ int g_part[256];
// pre-converted weights (fp16)
#define W_TOTAL 131072
__device__ __half g_w[W_TOTAL];
#define OFF_WQ 0
#define OFF_WK 16384
#define OFF_WV 32768
#define OFF_WO 49152
#define OFF_W1 65536
#define OFF_W2 98304

// ---------------- helpers ----------------
__device__ __forceinline__ uint32_t smem_u32(const void* p) {
    uint32_t a;
    asm("{ .reg .u64 t; cvta.to.shared.u64 t, %1; cvt.u32.u64 %0, t; }" : "=r"(a) : "l"(p));
    return a;
}
__device__ __forceinline__ void ldm_x4(uint32_t& a0, uint32_t& a1, uint32_t& a2, uint32_t& a3,
                                       uint32_t addr) {
    asm volatile("ldmatrix.sync.aligned.m8n8.x4.shared.b16 {%0,%1,%2,%3}, [%4];"
                 : "=r"(a0), "=r"(a1), "=r"(a2), "=r"(a3) : "r"(addr));
}
__device__ __forceinline__ void ldm_x2(uint32_t& b0, uint32_t& b1, uint32_t addr) {
    asm volatile("ldmatrix.sync.aligned.m8n8.x2.shared.b16 {%0,%1}, [%2];"
                 : "=r"(b0), "=r"(b1) : "r"(addr));
}
__device__ __forceinline__ void mma_f16(float* c, uint32_t a0, uint32_t a1, uint32_t a2,
                                        uint32_t a3, uint32_t b0, uint32_t b1) {
    asm volatile(
        "mma.sync.aligned.m16n8k16.row.col.f32.f16.f16.f32 "
        "{%0,%1,%2,%3}, {%4,%5,%6,%7}, {%8,%9}, {%0,%1,%2,%3};"
        : "+f"(c[0]), "+f"(c[1]), "+f"(c[2]), "+f"(c[3])
        : "r"(a0), "r"(a1), "r"(a2), "r"(a3), "r"(b0), "r"(b1));
}
__device__ __forceinline__ uint32_t pack_h2(float a, float b) {
    uint32_t r;
    asm("cvt.rn.f16x2.f32 %0, %1, %2;" : "=r"(r) : "f"(b), "f"(a));
    return r;
}
__device__ __forceinline__ void cp16(uint32_t dst, const void* src) {
    asm volatile("cp.async.cg.shared.global [%0], [%1], 16;" :: "r"(dst), "l"(src));
}
__device__ __forceinline__ void cp16z(uint32_t dst, const void* src, bool pred) {
    int sz = pred ? 16 : 0;
    asm volatile("cp.async.cg.shared.global [%0], [%1], 16, %2;"
                 :: "r"(dst), "l"(src), "r"(sz));
}
#define CP_COMMIT() asm volatile("cp.async.commit_group;" ::: "memory")
#define CP_WAIT0()  asm volatile("cp.async.wait_group 0;" ::: "memory")
#define CP_WAIT1()  asm volatile("cp.async.wait_group 1;" ::: "memory")

// ---------------- fused prep: stats zero + weight convert + h convert ----------
__global__ void prep_kernel(const float* __restrict__ h,
                            const float* __restrict__ WQ, const float* __restrict__ WK,
                            const float* __restrict__ WV, const float* __restrict__ WO,
                            const float* __restrict__ W1, const float* __restrict__ W2,
                            int npair)
{
    int gid = blockIdx.x * blockDim.x + threadIdx.x;
    if (gid < npair) {
        float2 v = ((const float2*)h)[gid];
        g_hh[gid] = pack_h2(v.x, v.y);
    }
    if (gid < W_TOTAL / 2) {
        int elem = gid * 2;
        const float* src;
        int local;
        if (elem < OFF_W1) {
            int m = elem >> 14;
            local = elem & 16383;
            src = (m == 0) ? WQ : (m == 1) ? WK : (m == 2) ? WV : WO;
        } else if (elem < OFF_W2) {
            local = elem - OFF_W1;
            src = W1;
        } else {
            local = elem - OFF_W2;
            src = W2;
        }
        ((uint32_t*)g_w)[gid] = pack_h2(src[local], src[local + 1]);
    }
    if (gid < 4 * D) g_stats[gid] = 0.f;
}

// ---------------- CSR build (side stream) ----------------
__global__ void zero_cursor(int n) {
    int i = blockIdx.x * blockDim.x + threadIdx.x;
    if (i < n) g_cursor[i] = 0;
}

__global__ void hist_kernel(const int* __restrict__ dst, int E) {
    int q = blockIdx.x * blockDim.x + threadIdx.x;
    int e = q * 4;
    if (e + 4 <= E) {
        int4 d4 = *(const int4*)(dst + e);
        atomicAdd(&g_cursor[d4.x], 1);
        atomicAdd(&g_cursor[d4.y], 1);
        atomicAdd(&g_cursor[d4.z], 1);
        atomicAdd(&g_cursor[d4.w], 1);
    } else {
        for (int i = e; i < E; ++i) atomicAdd(&g_cursor[dst[i]], 1);
    }
}

__global__ __launch_bounds__(256) void scan_local(int n) {
    int tid = threadIdx.x;
    int lane = tid & 31;
    int wid = tid >> 5;
    int i = blockIdx.x * 256 + tid;
    int c = (i < n) ? g_cursor[i] : 0;
    int v = c;
#pragma unroll
    for (int o = 1; o < 32; o <<= 1) {
        int t = __shfl_up_sync(0xffffffffu, v, o);
        if (lane >= o) v += t;
    }
    __shared__ int wsum[8];
    if (lane == 31) wsum[wid] = v;
    __syncthreads();
    if (wid == 0 && lane < 8) {
        int w = wsum[lane];
#pragma unroll
        for (int o = 1; o < 8; o <<= 1) {
            int t = __shfl_up_sync(0xffu, w, o);
            if (lane >= o) w += t;
        }
        wsum[lane] = w;
    }
    __syncthreads();
    int off = (wid > 0) ? wsum[wid - 1] : 0;
    if (i < n) g_rowptr[i] = v - c + off;
    if (tid == 255) g_part[blockIdx.x] = v + off;
}

__global__ __launch_bounds__(256) void scan_final(int n, int E) {
    int tid = threadIdx.x;
    int lane = tid & 31;
    int wid = tid >> 5;
    int nb = gridDim.x;
    int p = (tid < nb && tid < (int)blockIdx.x) ? g_part[tid] : 0;
#pragma unroll
    for (int o = 16; o > 0; o >>= 1) p += __shfl_xor_sync(0xffffffffu, p, o);
    __shared__ int wsum[8];
    __shared__ int s_off;
    if (lane == 0) wsum[wid] = p;
    __syncthreads();
    if (tid == 0) {
        int s = 0;
#pragma unroll
        for (int w = 0; w < 8; ++w) s += wsum[w];
        s_off = s;
    }
    __syncthreads();
    int i = blockIdx.x * 256 + tid;
    if (i < n) {
        int r = g_rowptr[i] + s_off;
        g_rowptr[i] = r;
        g_cursor[i] = r;
    }
    if (i == 0) g_rowptr[n] = E;
}

__global__ void scatter_kernel(const int* __restrict__ src, const int* __restrict__ dst, int E) {
    int q = blockIdx.x * blockDim.x + threadIdx.x;
    int e = q * 4;
    if (e + 4 <= E) {
        int4 s4 = *(const int4*)(src + e);
        int4 d4 = *(const int4*)(dst + e);
        g_csrc[atomicAdd(&g_cursor[d4.x], 1)] = s4.x;
        g_csrc[atomicAdd(&g_cursor[d4.y], 1)] = s4.y;
        g_csrc[atomicAdd(&g_cursor[d4.z], 1)] = s4.z;
        g_csrc[atomicAdd(&g_cursor[d4.w], 1)] = s4.w;
    } else {
        for (int i = e; i < E; ++i)
            g_csrc[atomicAdd(&g_cursor[dst[i]], 1)] = src[i];
    }
}

// ---------------- gather attention: fp16 K/V, warp per node ----------------
__device__ __forceinline__ float4 unp4(uint2 u) {
    float2 a = __half22float2(*reinterpret_cast<const __half2*>(&u.x));
    float2 b = __half22float2(*reinterpret_cast<const __half2*>(&u.y));
    return make_float4(a.x, a.y, b.x, b.y);
}

__global__ __launch_bounds__(256) void gather_kernel(int n) {
    int warp = (blockIdx.x * blockDim.x + threadIdx.x) >> 5;
    if (warp >= n) return;
    const int lid = threadIdx.x & 31;
    const int d = warp;
    const size_t base = (size_t)d * (D / 2) + lid * 2;

    float4 q = unp4(*(const uint2*)(g_Qh + base));
    float4 acc = make_float4(0.f, 0.f, 0.f, 0.f);
    float zacc = 0.f;

    int beg = g_rowptr[d], end = g_rowptr[d + 1];
    int i = beg;
    for (; i + 2 <= end; i += 2) {
        int s0 = g_csrc[i], s1 = g_csrc[i + 1];
        size_t o0 = (size_t)s0 * (D / 2) + lid * 2;
        size_t o1 = (size_t)s1 * (D / 2) + lid * 2;
        float4 k0 = unp4(*(const uint2*)(g_Kh + o0));
        float4 k1 = unp4(*(const uint2*)(g_Kh + o1));
        float4 v0 = unp4(*(const uint2*)(g_Vh + o0));
        float4 v1 = unp4(*(const uint2*)(g_Vh + o1));
        float p0 = q.x * k0.x + q.y * k0.y + q.z * k0.z + q.w * k0.w;
        float p1 = q.x * k1.x + q.y * k1.y + q.z * k1.z + q.w * k1.w;
        p0 += __shfl_xor_sync(0xffffffffu, p0, 1);
        p1 += __shfl_xor_sync(0xffffffffu, p1, 1);
        p0 += __shfl_xor_sync(0xffffffffu, p0, 2);
        p1 += __shfl_xor_sync(0xffffffffu, p1, 2);
        float sc0 = __expf(fminf(fmaxf(p0 * 0.25f, -5.f), 5.f));
        float sc1 = __expf(fminf(fmaxf(p1 * 0.25f, -5.f), 5.f));
        acc.x += v0.x * sc0 + v1.x * sc1;
        acc.y += v0.y * sc0 + v1.y * sc1;
        acc.z += v0.z * sc0 + v1.z * sc1;
        acc.w += v0.w * sc0 + v1.w * sc1;
        zacc += sc0 + sc1;
    }
    if (i < end) {
        int s0 = g_csrc[i];
        size_t o0 = (size_t)s0 * (D / 2) + lid * 2;
        float4 k0 = unp4(*(const uint2*)(g_Kh + o0));
        float4 v0 = unp4(*(const uint2*)(g_Vh + o0));
        float p0 = q.x * k0.x + q.y * k0.y + q.z * k0.z + q.w * k0.w;
        p0 += __shfl_xor_sync(0xffffffffu, p0, 1);
        p0 += __shfl_xor_sync(0xffffffffu, p0, 2);
        float sc0 = __expf(fminf(fmaxf(p0 * 0.25f, -5.f), 5.f));
        acc.x += v0.x * sc0; acc.y += v0.y * sc0;
        acc.z += v0.z * sc0; acc.w += v0.w * sc0;
        zacc += sc0;
    }
    float inv = 1.0f / zacc;
    *(uint2*)(g_attn + base) = make_uint2(pack_h2(acc.x * inv, acc.y * inv),
                                          pack_h2(acc.z * inv, acc.w * inv));
}

// ---------------- tensor-core GEMM: 128x128 tile, fp16, 2-stage pipeline --------
enum { EPI_STORE = 0, EPI_RESID = 1, EPI_RELU = 2 };

#define BK 64
#define SK 72
#define TILEB (128 * SK * 2)
#define STAGE_B (2 * TILEB)
#define DSMEM_BYTES (2 * STAGE_B)

template <int EPI, bool STATS, bool RESBN, bool OUTH, int KT>
__device__ __forceinline__ void tgemm_core(
    const __half* __restrict__ A, const __half* __restrict__ W,
    const float* __restrict__ bias,
    const uint32_t* __restrict__ resh,          // fp16-pair residual source
    const float* __restrict__ t0, const float* __restrict__ t1,
    float* __restrict__ ssum, float* __restrict__ ssq,
    float* __restrict__ Cf, uint32_t* __restrict__ Ch,
    int M, int ldc, int rowBase, int colBase)
{
    extern __shared__ __align__(16) char sm[];
    const uint32_t smbase = smem_u32(sm);

    const int tid = threadIdx.x;
    const int wid = tid >> 5;
    const int lid = tid & 31;
    const int warp_m = wid & 1;
    const int warp_n = wid >> 1;

    const int ar = (lid & 7) + ((lid >> 3) & 1) * 8;
    const int ac = (lid >> 4) * 8;
    const int br = lid & 7;
    const int bc = ((lid >> 3) & 1) * 8;

    const uint32_t aOff = (uint32_t)((warp_m * 64 + ar) * SK + ac) * 2;
    const uint32_t bOff = (uint32_t)((warp_n * 32 + br) * SK + bc) * 2;

    float acc[4][4][4];
#pragma unroll
    for (int i = 0; i < 4; ++i)
#pragma unroll
        for (int j = 0; j < 4; ++j)
#pragma unroll
            for (int t = 0; t < 4; ++t) acc[i][j][t] = 0.f;

    const int row = tid >> 1;
    const int kh = (tid & 1) * 32;
    const int grow = rowBase + row;
    const bool valid = grow < M;

    const __half* pA = A + (size_t)grow * KT + kh;
    const __half* pW = W + (size_t)(colBase + row) * KT + kh;
    const uint32_t sdst = (uint32_t)(row * SK + kh) * 2;

    auto load_slab = [&](int slab, int stage) {
        uint32_t sb = smbase + stage * STAGE_B + sdst;
        const __half* a = pA + slab * BK;
        const __half* w = pW + slab * BK;
#pragma unroll
        for (int c = 0; c < 4; ++c) cp16z(sb + c * 16, a + c * 8, valid);
#pragma unroll
        for (int c = 0; c < 4; ++c) cp16(sb + TILEB + c * 16, w + c * 8);
        CP_COMMIT();
    };

    constexpr int NSLAB = KT / BK;
    load_slab(0, 0);
#pragma unroll
    for (int s = 0; s < NSLAB; ++s) {
        if (s + 1 < NSLAB) {
            load_slab(s + 1, (s + 1) & 1);
            CP_WAIT1();
        } else {
            CP_WAIT0();
        }
        __syncthreads();

        const uint32_t stA = smbase + (s & 1) * STAGE_B;
        const uint32_t stW = stA + TILEB;
#pragma unroll
        for (int ks = 0; ks < 4; ++ks) {
            const uint32_t k0 = (uint32_t)(ks * 16) * 2;
            uint32_t bh[4][2];
#pragma unroll
            for (int j = 0; j < 4; ++j)
                ldm_x2(bh[j][0], bh[j][1], stW + bOff + (uint32_t)(j * 8 * SK) * 2 + k0);
#pragma unroll
            for (int i = 0; i < 4; ++i) {
                uint32_t a0, a1, a2, a3;
                ldm_x4(a0, a1, a2, a3, stA + aOff + (uint32_t)(i * 16 * SK) * 2 + k0);
#pragma unroll
                for (int j = 0; j < 4; ++j)
                    mma_f16(acc[i][j], a0, a1, a2, a3, bh[j][0], bh[j][1]);
            }
        }
        if (s + 2 < NSLAB) __syncthreads();
    }

    // ---- epilogue ----
    const int rr = lid >> 2;
    const int cc = (lid & 3) * 2;
    float cs[8], cq[8];
    if (STATS) {
#pragma unroll
        for (int t = 0; t < 8; ++t) { cs[t] = 0.f; cq[t] = 0.f; }
    }
#pragma unroll
    for (int i = 0; i < 4; ++i) {
#pragma unroll
        for (int hf = 0; hf < 2; ++hf) {
            int r = rowBase + warp_m * 64 + i * 16 + rr + hf * 8;
            if (r >= M) continue;
#pragma unroll
            for (int j = 0; j < 4; ++j) {
                int col = colBase + warp_n * 32 + j * 8 + cc;
                float v0 = acc[i][j][hf * 2];
                float v1 = acc[i][j][hf * 2 + 1];
                if (EPI == EPI_RESID) {
                    v0 += bias[col];
                    v1 += bias[col + 1];
                    uint32_t rp = resh[((size_t)r * D + col) >> 1];
                    float2 rf = __half22float2(*reinterpret_cast<const __half2*>(&rp));
                    float r0 = rf.x, r1 = rf.y;
                    if (RESBN) {
                        r0 = r0 * t0[col] + t1[col];
                        r1 = r1 * t0[col + 1] + t1[col + 1];
                    }
                    v0 += r0; v1 += r1;
                } else if (EPI == EPI_RELU) {
                    v0 = fmaxf(v0 + bias[col], 0.f);
                    v1 = fmaxf(v1 + bias[col + 1], 0.f);
                }
                if (STATS) {
                    cs[j * 2] += v0;     cq[j * 2] += v0 * v0;
                    cs[j * 2 + 1] += v1; cq[j * 2 + 1] += v1 * v1;
                }
                if (OUTH) {
                    Ch[((size_t)r * ldc + col) >> 1] = pack_h2(v0, v1);
                } else {
                    *(float2*)(Cf + (size_t)r * ldc + col) = make_float2(v0, v1);
                }
            }
        }
    }
    if (STATS) {
#pragma unroll
        for (int t = 0; t < 8; ++t) {
#pragma unroll
            for (int o = 4; o < 32; o <<= 1) {
                cs[t] += __shfl_xor_sync(0xffffffffu, cs[t], o);
                cq[t] += __shfl_xor_sync(0xffffffffu, cq[t], o);
            }
        }
        if (lid < 4) {
#pragma unroll
            for (int t = 0; t < 8; ++t) {
                int col = colBase + warp_n * 32 + (t >> 1) * 8 + lid * 2 + (t & 1);
                atomicAdd(&ssum[col & (D - 1)], cs[t]);
                atomicAdd(&ssq[col & (D - 1)], cq[t]);
            }
        }
    }
}

template <int EPI, bool STATS, bool RESBN, bool OUTH, int KT>
__global__ __launch_bounds__(256, 2) void tgemm_k(
    const __half* __restrict__ A, const __half* __restrict__ W,
    const float* __restrict__ bias, const uint32_t* __restrict__ resh,
    const float* __restrict__ t0, const float* __restrict__ t1,
    float* __restrict__ ssum, float* __restrict__ ssq,
    float* __restrict__ Cf, uint32_t* __restrict__ Ch, int M, int ldc)
{
    tgemm_core<EPI, STATS, RESBN, OUTH, KT>(A, W, bias, resh, t0, t1, ssum, ssq, Cf, Ch,
                                            M, ldc, blockIdx.x * 128, blockIdx.y * 128);
}

__global__ __launch_bounds__(256, 2) void qkv_kernel(int M) {
    int off = (blockIdx.y == 0) ? OFF_WQ : (blockIdx.y == 1) ? OFF_WK : OFF_WV;
    uint32_t* C = (blockIdx.y == 0) ? g_Qh : (blockIdx.y == 1) ? g_Kh : g_Vh;
    tgemm_core<EPI_STORE, false, false, true, 128>(
        (const __half*)g_hh, g_w + off, nullptr, nullptr, nullptr, nullptr,
        nullptr, nullptr, nullptr, C, M, D, blockIdx.x * 128, 0);
}

// ---------------- BN1: fused finalize + convert (fp16 x1 input) ----------------
__global__ __launch_bounds__(256) void bn_convert(
    const uint32_t* __restrict__ x1h, const float* __restrict__ sum,
    const float* __restrict__ sq,
    const float* __restrict__ g, const float* __restrict__ b,
    float* __restrict__ bn_out, int npair, int M)
{
    __shared__ float s_sc[D], s_sh[D];
    int tid = threadIdx.x;
    if (tid < D) {
        float invM = 1.0f / (float)M;
        float mu = sum[tid] * invM;
        float var = sq[tid] * invM - mu * mu;
        float sc = g[tid] * rsqrtf(var + 1e-5f);
        s_sc[tid] = sc;
        s_sh[tid] = b[tid] - mu * sc;
        if (blockIdx.x == 0) {
            bn_out[tid] = sc;
            bn_out[D + tid] = s_sh[tid];
        }
    }
    __syncthreads();
    int p = blockIdx.x * blockDim.x + tid;
    if (p >= npair) return;
    uint32_t rp = x1h[p];
    float2 v = __half22float2(*reinterpret_cast<const __half2*>(&rp));
    int col = (p * 2) & (D - 1);
    g_bx1[p] = pack_h2(v.x * s_sc[col] + s_sh[col], v.y * s_sc[col + 1] + s_sh[col + 1]);
}

// bn_apply with inline BN2 finalize + float4 I/O
__global__ __launch_bounds__(256) void bn_apply(
    const float* __restrict__ x, const float* __restrict__ sum, const float* __restrict__ sq,
    const float* __restrict__ g, const float* __restrict__ b,
    float* __restrict__ out, int M)
{
    __shared__ float s_sc[D], s_sh[D];
    int tid = threadIdx.x;
    if (tid < D) {
        float invM = 1.0f / (float)M;
        float mu = sum[tid] * invM;
        float var = sq[tid] * invM - mu * mu;
        float sc = g[tid] * rsqrtf(var + 1e-5f);
        s_sc[tid] = sc;
        s_sh[tid] = b[tid] - mu * sc;
    }
    __syncthreads();
    int total4 = M * D / 4;
    int stride = gridDim.x * blockDim.x;
    for (int i = blockIdx.x * blockDim.x + tid; i < total4; i += stride) {
        float4 v = ((const float4*)x)[i];
        int col = (i * 4) & (D - 1);
        v.x = v.x * s_sc[col] + s_sh[col];
        v.y = v.y * s_sc[col + 1] + s_sh[col + 1];
        v.z = v.z * s_sc[col + 2] + s_sh[col + 2];
        v.w = v.w * s_sc[col + 3] + s_sh[col + 3];
        ((float4*)out)[i] = v;
    }
}

// ---------------- host launch ----------------
static cudaStream_t g_s1 = nullptr;
static cudaEvent_t g_e0 = nullptr, g_e1 = nullptr;

extern "C" void kernel_launch(void* const* d_in, const int* in_sizes, int n_in,
                              void* d_out, int out_size)
{
    const float* h    = (const float*)d_in[0];
    const int*   src  = (const int*)d_in[1];
    const int*   dst  = (const int*)d_in[2];
    const float* WQ   = (const float*)d_in[3];
    const float* WK   = (const float*)d_in[4];
    const float* WV   = (const float*)d_in[5];
    const float* WO   = (const float*)d_in[6];
    const float* bO   = (const float*)d_in[7];
    const float* W1   = (const float*)d_in[8];
    const float* b1   = (const float*)d_in[9];
    const float* W2   = (const float*)d_in[10];
    const float* b2   = (const float*)d_in[11];
    const float* bn1g = (const float*)d_in[12];
    const float* bn1b = (const float*)d_in[13];
    const float* bn2g = (const float*)d_in[14];
    const float* bn2b = (const float*)d_in[15];
    float* out = (float*)d_out;

    int M = in_sizes[0] / D;
    int E = in_sizes[1];
    if (M > N_NODES) M = N_NODES;
    if (E > N_EDGES) E = N_EDGES;

    float *x2p, *stp, *bn1p;
    uint32_t *attnp, *x1hp, *bx1p, *midp, *hhp;
    __half *wp;
    cudaGetSymbolAddress((void**)&x2p, g_x2);
    cudaGetSymbolAddress((void**)&stp, g_stats);
    cudaGetSymbolAddress((void**)&bn1p, g_bn1);
    cudaGetSymbolAddress((void**)&attnp, g_attn);
    cudaGetSymbolAddress((void**)&x1hp, g_x1h);
    cudaGetSymbolAddress((void**)&bx1p, g_bx1);
    cudaGetSymbolAddress((void**)&midp, g_midh);
    cudaGetSymbolAddress((void**)&hhp, g_hh);
    cudaGetSymbolAddress((void**)&wp, g_w);

    cudaFuncSetAttribute(qkv_kernel, cudaFuncAttributeMaxDynamicSharedMemorySize, DSMEM_BYTES);
    cudaFuncSetAttribute(tgemm_k<EPI_RESID, true, false, true, 128>,
                         cudaFuncAttributeMaxDynamicSharedMemorySize, DSMEM_BYTES);
    cudaFuncSetAttribute(tgemm_k<EPI_RELU, false, false, true, 128>,
                         cudaFuncAttributeMaxDynamicSharedMemorySize, DSMEM_BYTES);
    cudaFuncSetAttribute(tgemm_k<EPI_RESID, true, true, false, 256>,
                         cudaFuncAttributeMaxDynamicSharedMemorySize, DSMEM_BYTES);

    if (g_s1 == nullptr) {
        if (cudaStreamCreateWithFlags(&g_s1, cudaStreamNonBlocking) != cudaSuccess)
            g_s1 = nullptr;
        cudaEventCreateWithFlags(&g_e0, cudaEventDisableTiming);
        cudaEventCreateWithFlags(&g_e1, cudaEventDisableTiming);
    }
    cudaStream_t s1 = g_s1 ? g_s1 : (cudaStream_t)0;

    dim3 blk(256);
    int gx = (M + 127) / 128;
    int nb = (M + 255) / 256;
    int npair = M * D / 2;
    int cvb = (npair + 255) / 256;
    int e4 = (E + 3) / 4;

    // fork: CSR chain on side stream, overlapped with prep + QKV
    cudaEventRecord(g_e0, 0);
    cudaStreamWaitEvent(s1, g_e0, 0);

    zero_cursor<<<nb, 256, 0, s1>>>(M);
    hist_kernel<<<(e4 + 255) / 256, 256, 0, s1>>>(dst, E);
    scan_local<<<nb, 256, 0, s1>>>(M);
    scan_final<<<nb, 256, 0, s1>>>(M, E);
    scatter_kernel<<<(e4 + 255) / 256, 256, 0, s1>>>(src, dst, E);
    cudaEventRecord(g_e1, s1);

    prep_kernel<<<cvb, 256>>>(h, WQ, WK, WV, WO, W1, W2, npair);
    qkv_kernel<<<dim3(gx, 3), blk, DSMEM_BYTES>>>(M);

    cudaStreamWaitEvent(0, g_e1, 0);

    gather_kernel<<<(M * 32 + 255) / 256, 256>>>(M);

    // O projection: attn @ WO^T + bO + h(fp16) -> x1 fp16 (+ BN1 stats)
    tgemm_k<EPI_RESID, true, false, true, 128><<<dim3(gx, 1), blk, DSMEM_BYTES>>>(
        (const __half*)attnp, wp + OFF_WO, bO, hhp, nullptr, nullptr,
        stp, stp + D, nullptr, x1hp, M, D);

    bn_convert<<<cvb, 256>>>(x1hp, stp, stp + D, bn1g, bn1b, bn1p, npair, M);

    // FFN1: relu(BN1(x1) @ W1^T + b1) -> mid fp16 [N, 256]
    tgemm_k<EPI_RELU, false, false, true, 128><<<dim3(gx, 2), blk, DSMEM_BYTES>>>(
        (const __half*)bx1p, wp + OFF_W1, b1, nullptr, nullptr, nullptr,
        nullptr, nullptr, nullptr, midp, M, 2 * D);

    // FFN2: mid @ W2^T + b2 + BN1(x1 fp16) -> x2 fp32 (+ BN2 stats)
    tgemm_k<EPI_RESID, true, true, false, 256><<<dim3(gx, 1), blk, DSMEM_BYTES>>>(
        (const __half*)midp, wp + OFF_W2, b2, x1hp, bn1p, bn1p + D,
        stp + 2 * D, stp + 3 * D, x2p, nullptr, M, D);

    bn_apply<<<1024, 256>>>(x2p, stp + 2 * D, stp + 3 * D, bn2g, bn2b, out, M);
}

// round 16
// speedup vs baseline: 1.6607x; 1.0435x over previous
#include <cuda_runtime.h>
#include <cuda_fp16.h>
#include <math.h>
#include <stdint.h>

#define N_NODES 50000
#define N_EDGES 640000
#define D 128
#define H 8

// ---------------- scratch (static device globals; no allocation) ----------------
__device__ float g_x2[N_NODES * D];
__device__ float g_stats[4 * D];
__device__ float g_bn1[2 * D];
// fp16x2-packed buffers
__device__ uint32_t g_Qh [N_NODES * D / 2];
__device__ uint32_t g_Kh [N_NODES * D / 2];
__device__ uint32_t g_Vh [N_NODES * D / 2];
__device__ uint32_t g_attn[N_NODES * D / 2];
__device__ uint32_t g_hh [N_NODES * D / 2];
__device__ uint32_t g_x1h[N_NODES * D / 2];
__device__ uint32_t g_bx1[N_NODES * D / 2];
__device__ uint32_t g_midh[N_NODES * D];
// CSR
__device__ int g_rowptr[N_NODES + 1];
__device__ int g_cursor[N_NODES];
__device__ int g_csrc[N_EDGES];
__device__ int g_part[256];
// pre-converted weights (fp16)
#define W_TOTAL 131072
__device__ __half g_w[W_TOTAL];
#define OFF_WQ 0
#define OFF_WK 16384
#define OFF_WV 32768
#define OFF_WO 49152
#define OFF_W1 65536
#define OFF_W2 98304

// ---------------- helpers ----------------
__device__ __forceinline__ uint32_t smem_u32(const void* p) {
    uint32_t a;
    asm("{ .reg .u64 t; cvta.to.shared.u64 t, %1; cvt.u32.u64 %0, t; }" : "=r"(a) : "l"(p));
    return a;
}
__device__ __forceinline__ void ldm_x4(uint32_t& a0, uint32_t& a1, uint32_t& a2, uint32_t& a3,
                                       uint32_t addr) {
    asm volatile("ldmatrix.sync.aligned.m8n8.x4.shared.b16 {%0,%1,%2,%3}, [%4];"
                 : "=r"(a0), "=r"(a1), "=r"(a2), "=r"(a3) : "r"(addr));
}
__device__ __forceinline__ void ldm_x2(uint32_t& b0, uint32_t& b1, uint32_t addr) {
    asm volatile("ldmatrix.sync.aligned.m8n8.x2.shared.b16 {%0,%1}, [%2];"
                 : "=r"(b0), "=r"(b1) : "r"(addr));
}
__device__ __forceinline__ void mma_f16(float* c, uint32_t a0, uint32_t a1, uint32_t a2,
                                        uint32_t a3, uint32_t b0, uint32_t b1) {
    asm volatile(
        "mma.sync.aligned.m16n8k16.row.col.f32.f16.f16.f32 "
        "{%0,%1,%2,%3}, {%4,%5,%6,%7}, {%8,%9}, {%0,%1,%2,%3};"
        : "+f"(c[0]), "+f"(c[1]), "+f"(c[2]), "+f"(c[3])
        : "r"(a0), "r"(a1), "r"(a2), "r"(a3), "r"(b0), "r"(b1));
}
__device__ __forceinline__ uint32_t pack_h2(float a, float b) {
    uint32_t r;
    asm("cvt.rn.f16x2.f32 %0, %1, %2;" : "=r"(r) : "f"(b), "f"(a));
    return r;
}
__device__ __forceinline__ void cp16(uint32_t dst, const void* src) {
    asm volatile("cp.async.cg.shared.global [%0], [%1], 16;" :: "r"(dst), "l"(src));
}
__device__ __forceinline__ void cp16ca(uint32_t dst, const void* src) {
    asm volatile("cp.async.ca.shared.global [%0], [%1], 16;" :: "r"(dst), "l"(src));
}
__device__ __forceinline__ void cp16z(uint32_t dst, const void* src, bool pred) {
    int sz = pred ? 16 : 0;
    asm volatile("cp.async.cg.shared.global [%0], [%1], 16, %2;"
                 :: "r"(dst), "l"(src), "r"(sz));
}
#define CP_COMMIT() asm volatile("cp.async.commit_group;" ::: "memory")
#define CP_WAIT0()  asm volatile("cp.async.wait_group 0;" ::: "memory")
#define CP_WAIT1()  asm volatile("cp.async.wait_group 1;" ::: "memory")

// ---------------- fused prep: stats zero + weight convert + h convert ----------
__global__ void prep_kernel(const float* __restrict__ h,
                            const float* __restrict__ WQ, const float* __restrict__ WK,
                            const float* __restrict__ WV, const float* __restrict__ WO,
                            const float* __restrict__ W1, const float* __restrict__ W2,
                            int npair)
{
    int gid = blockIdx.x * blockDim.x + threadIdx.x;
    if (gid < npair) {
        float2 v = ((const float2*)h)[gid];
        g_hh[gid] = pack_h2(v.x, v.y);
    }
    if (gid < W_TOTAL / 2) {
        int elem = gid * 2;
        const float* src;
        int local;
        if (elem < OFF_W1) {
            int m = elem >> 14;
            local = elem & 16383;
            src = (m == 0) ? WQ : (m == 1) ? WK : (m == 2) ? WV : WO;
        } else if (elem < OFF_W2) {
            local = elem - OFF_W1;
            src = W1;
        } else {
            local = elem - OFF_W2;
            src = W2;
        }
        ((uint32_t*)g_w)[gid] = pack_h2(src[local], src[local + 1]);
    }
    if (gid < 4 * D) g_stats[gid] = 0.f;
}

// ---------------- CSR build (side stream) ----------------
__global__ void zero_cursor(int n) {
    int i = blockIdx.x * blockDim.x + threadIdx.x;
    if (i < n) g_cursor[i] = 0;
}

__global__ void hist_kernel(const int* __restrict__ dst, int E) {
    int q = blockIdx.x * blockDim.x + threadIdx.x;
    int e = q * 4;
    if (e + 4 <= E) {
        int4 d4 = *(const int4*)(dst + e);
        atomicAdd(&g_cursor[d4.x], 1);
        atomicAdd(&g_cursor[d4.y], 1);
        atomicAdd(&g_cursor[d4.z], 1);
        atomicAdd(&g_cursor[d4.w], 1);
    } else {
        for (int i = e; i < E; ++i) atomicAdd(&g_cursor[dst[i]], 1);
    }
}

__global__ __launch_bounds__(256) void scan_local(int n) {
    int tid = threadIdx.x;
    int lane = tid & 31;
    int wid = tid >> 5;
    int i = blockIdx.x * 256 + tid;
    int c = (i < n) ? g_cursor[i] : 0;
    int v = c;
#pragma unroll
    for (int o = 1; o < 32; o <<= 1) {
        int t = __shfl_up_sync(0xffffffffu, v, o);
        if (lane >= o) v += t;
    }
    __shared__ int wsum[8];
    if (lane == 31) wsum[wid] = v;
    __syncthreads();
    if (wid == 0 && lane < 8) {
        int w = wsum[lane];
#pragma unroll
        for (int o = 1; o < 8; o <<= 1) {
            int t = __shfl_up_sync(0xffu, w, o);
            if (lane >= o) w += t;
        }
        wsum[lane] = w;
    }
    __syncthreads();
    int off = (wid > 0) ? wsum[wid - 1] : 0;
    if (i < n) g_rowptr[i] = v - c + off;
    if (tid == 255) g_part[blockIdx.x] = v + off;
}

__global__ __launch_bounds__(256) void scan_final(int n, int E) {
    int tid = threadIdx.x;
    int lane = tid & 31;
    int wid = tid >> 5;
    int nb = gridDim.x;
    int p = (tid < nb && tid < (int)blockIdx.x) ? g_part[tid] : 0;
#pragma unroll
    for (int o = 16; o > 0; o >>= 1) p += __shfl_xor_sync(0xffffffffu, p, o);
    __shared__ int wsum[8];
    __shared__ int s_off;
    if (lane == 0) wsum[wid] = p;
    __syncthreads();
    if (tid == 0) {
        int s = 0;
#pragma unroll
        for (int w = 0; w < 8; ++w) s += wsum[w];
        s_off = s;
    }
    __syncthreads();
    int i = blockIdx.x * 256 + tid;
    if (i < n) {
        int r = g_rowptr[i] + s_off;
        g_rowptr[i] = r;
        g_cursor[i] = r;
    }
    if (i == 0) g_rowptr[n] = E;
}

__global__ void scatter_kernel(const int* __restrict__ src, const int* __restrict__ dst, int E) {
    int q = blockIdx.x * blockDim.x + threadIdx.x;
    int e = q * 4;
    if (e + 4 <= E) {
        int4 s4 = *(const int4*)(src + e);
        int4 d4 = *(const int4*)(dst + e);
        g_csrc[atomicAdd(&g_cursor[d4.x], 1)] = s4.x;
        g_csrc[atomicAdd(&g_cursor[d4.y], 1)] = s4.y;
        g_csrc[atomicAdd(&g_cursor[d4.z], 1)] = s4.z;
        g_csrc[atomicAdd(&g_cursor[d4.w], 1)] = s4.w;
    } else {
        for (int i = e; i < E; ++i)
            g_csrc[atomicAdd(&g_cursor[dst[i]], 1)] = src[i];
    }
}

// ---------------- gather attention: fp16 K/V, warp per node, 4-wide unroll ------
__device__ __forceinline__ float4 unp4(uint2 u) {
    float2 a = __half22float2(*reinterpret_cast<const __half2*>(&u.x));
    float2 b = __half22float2(*reinterpret_cast<const __half2*>(&u.y));
    return make_float4(a.x, a.y, b.x, b.y);
}

__global__ __launch_bounds__(256) void gather_kernel(int n) {
    int warp = (blockIdx.x * blockDim.x + threadIdx.x) >> 5;
    if (warp >= n) return;
    const int lid = threadIdx.x & 31;
    const int d = warp;
    const size_t base = (size_t)d * (D / 2) + lid * 2;

    float4 q = unp4(*(const uint2*)(g_Qh + base));
    float4 acc = make_float4(0.f, 0.f, 0.f, 0.f);
    float zacc = 0.f;

    int beg = g_rowptr[d], end = g_rowptr[d + 1];
    int i = beg;
    // 4-wide main loop: 8 outstanding K/V loads for latency hiding
    for (; i + 4 <= end; i += 4) {
        int s0 = g_csrc[i], s1 = g_csrc[i + 1], s2 = g_csrc[i + 2], s3 = g_csrc[i + 3];
        size_t o0 = (size_t)s0 * (D / 2) + lid * 2;
        size_t o1 = (size_t)s1 * (D / 2) + lid * 2;
        size_t o2 = (size_t)s2 * (D / 2) + lid * 2;
        size_t o3 = (size_t)s3 * (D / 2) + lid * 2;
        float4 k0 = unp4(*(const uint2*)(g_Kh + o0));
        float4 k1 = unp4(*(const uint2*)(g_Kh + o1));
        float4 k2 = unp4(*(const uint2*)(g_Kh + o2));
        float4 k3 = unp4(*(const uint2*)(g_Kh + o3));
        float4 v0 = unp4(*(const uint2*)(g_Vh + o0));
        float4 v1 = unp4(*(const uint2*)(g_Vh + o1));
        float4 v2 = unp4(*(const uint2*)(g_Vh + o2));
        float4 v3 = unp4(*(const uint2*)(g_Vh + o3));
        float p0 = q.x * k0.x + q.y * k0.y + q.z * k0.z + q.w * k0.w;
        float p1 = q.x * k1.x + q.y * k1.y + q.z * k1.z + q.w * k1.w;
        float p2 = q.x * k2.x + q.y * k2.y + q.z * k2.z + q.w * k2.w;
        float p3 = q.x * k3.x + q.y * k3.y + q.z * k3.z + q.w * k3.w;
        p0 += __shfl_xor_sync(0xffffffffu, p0, 1);
        p1 += __shfl_xor_sync(0xffffffffu, p1, 1);
        p2 += __shfl_xor_sync(0xffffffffu, p2, 1);
        p3 += __shfl_xor_sync(0xffffffffu, p3, 1);
        p0 += __shfl_xor_sync(0xffffffffu, p0, 2);
        p1 += __shfl_xor_sync(0xffffffffu, p1, 2);
        p2 += __shfl_xor_sync(0xffffffffu, p2, 2);
        p3 += __shfl_xor_sync(0xffffffffu, p3, 2);
        float sc0 = __expf(fminf(fmaxf(p0 * 0.25f, -5.f), 5.f));
        float sc1 = __expf(fminf(fmaxf(p1 * 0.25f, -5.f), 5.f));
        float sc2 = __expf(fminf(fmaxf(p2 * 0.25f, -5.f), 5.f));
        float sc3 = __expf(fminf(fmaxf(p3 * 0.25f, -5.f), 5.f));
        acc.x += v0.x * sc0 + v1.x * sc1 + v2.x * sc2 + v3.x * sc3;
        acc.y += v0.y * sc0 + v1.y * sc1 + v2.y * sc2 + v3.y * sc3;
        acc.z += v0.z * sc0 + v1.z * sc1 + v2.z * sc2 + v3.z * sc3;
        acc.w += v0.w * sc0 + v1.w * sc1 + v2.w * sc2 + v3.w * sc3;
        zacc += (sc0 + sc1) + (sc2 + sc3);
    }
    for (; i < end; ++i) {
        int s0 = g_csrc[i];
        size_t o0 = (size_t)s0 * (D / 2) + lid * 2;
        float4 k0 = unp4(*(const uint2*)(g_Kh + o0));
        float4 v0 = unp4(*(const uint2*)(g_Vh + o0));
        float p0 = q.x * k0.x + q.y * k0.y + q.z * k0.z + q.w * k0.w;
        p0 += __shfl_xor_sync(0xffffffffu, p0, 1);
        p0 += __shfl_xor_sync(0xffffffffu, p0, 2);
        float sc0 = __expf(fminf(fmaxf(p0 * 0.25f, -5.f), 5.f));
        acc.x += v0.x * sc0; acc.y += v0.y * sc0;
        acc.z += v0.z * sc0; acc.w += v0.w * sc0;
        zacc += sc0;
    }
    float inv = 1.0f / zacc;
    *(uint2*)(g_attn + base) = make_uint2(pack_h2(acc.x * inv, acc.y * inv),
                                          pack_h2(acc.z * inv, acc.w * inv));
}

// ---------------- tensor-core GEMM: 128x128 tile, fp16, 2-stage pipeline --------
enum { EPI_STORE = 0, EPI_RESID = 1, EPI_RELU = 2 };

#define BK 64
#define SK 72
#define TILEB (128 * SK * 2)
#define STAGE_B (2 * TILEB)
#define DSMEM_BYTES (2 * STAGE_B)

template <int EPI, bool STATS, bool RESBN, bool OUTH, int KT>
__device__ __forceinline__ void tgemm_core(
    const __half* __restrict__ A, const __half* __restrict__ W,
    const float* __restrict__ bias,
    const uint32_t* __restrict__ resh,
    const float* __restrict__ t0, const float* __restrict__ t1,
    float* __restrict__ ssum, float* __restrict__ ssq,
    float* __restrict__ Cf, uint32_t* __restrict__ Ch,
    int M, int ldc, int rowBase, int colBase)
{
    extern __shared__ __align__(16) char sm[];
    const uint32_t smbase = smem_u32(sm);

    const int tid = threadIdx.x;
    const int wid = tid >> 5;
    const int lid = tid & 31;
    const int warp_m = wid & 1;
    const int warp_n = wid >> 1;

    const int ar = (lid & 7) + ((lid >> 3) & 1) * 8;
    const int ac = (lid >> 4) * 8;
    const int br = lid & 7;
    const int bc = ((lid >> 3) & 1) * 8;

    const uint32_t aOff = (uint32_t)((warp_m * 64 + ar) * SK + ac) * 2;
    const uint32_t bOff = (uint32_t)((warp_n * 32 + br) * SK + bc) * 2;

    float acc[4][4][4];
#pragma unroll
    for (int i = 0; i < 4; ++i)
#pragma unroll
        for (int j = 0; j < 4; ++j)
#pragma unroll
            for (int t = 0; t < 4; ++t) acc[i][j][t] = 0.f;

    const int row = tid >> 1;
    const int kh = (tid & 1) * 32;
    const int grow = rowBase + row;
    const bool valid = grow < M;

    const __half* pA = A + (size_t)grow * KT + kh;
    const __half* pW = W + (size_t)(colBase + row) * KT + kh;
    const uint32_t sdst = (uint32_t)(row * SK + kh) * 2;

    auto load_slab = [&](int slab, int stage) {
        uint32_t sb = smbase + stage * STAGE_B + sdst;
        const __half* a = pA + slab * BK;
        const __half* w = pW + slab * BK;
#pragma unroll
        for (int c = 0; c < 4; ++c) cp16z(sb + c * 16, a + c * 8, valid);
        // W tiles: L1-cached — co-resident CTAs re-read the same rows
#pragma unroll
        for (int c = 0; c < 4; ++c) cp16ca(sb + TILEB + c * 16, w + c * 8);
        CP_COMMIT();
    };

    constexpr int NSLAB = KT / BK;
    load_slab(0, 0);
#pragma unroll
    for (int s = 0; s < NSLAB; ++s) {
        if (s + 1 < NSLAB) {
            load_slab(s + 1, (s + 1) & 1);
            CP_WAIT1();
        } else {
            CP_WAIT0();
        }
        __syncthreads();

        const uint32_t stA = smbase + (s & 1) * STAGE_B;
        const uint32_t stW = stA + TILEB;
#pragma unroll
        for (int ks = 0; ks < 4; ++ks) {
            const uint32_t k0 = (uint32_t)(ks * 16) * 2;
            uint32_t bh[4][2];
#pragma unroll
            for (int j = 0; j < 4; ++j)
                ldm_x2(bh[j][0], bh[j][1], stW + bOff + (uint32_t)(j * 8 * SK) * 2 + k0);
#pragma unroll
            for (int i = 0; i < 4; ++i) {
                uint32_t a0, a1, a2, a3;
                ldm_x4(a0, a1, a2, a3, stA + aOff + (uint32_t)(i * 16 * SK) * 2 + k0);
#pragma unroll
                for (int j = 0; j < 4; ++j)
                    mma_f16(acc[i][j], a0, a1, a2, a3, bh[j][0], bh[j][1]);
            }
        }
        if (s + 2 < NSLAB) __syncthreads();
    }

    // ---- epilogue ----
    const int rr = lid >> 2;
    const int cc = (lid & 3) * 2;
    float cs[8], cq[8];
    if (STATS) {
#pragma unroll
        for (int t = 0; t < 8; ++t) { cs[t] = 0.f; cq[t] = 0.f; }
    }
#pragma unroll
    for (int i = 0; i < 4; ++i) {
#pragma unroll
        for (int hf = 0; hf < 2; ++hf) {
            int r = rowBase + warp_m * 64 + i * 16 + rr + hf * 8;
            if (r >= M) continue;
#pragma unroll
            for (int j = 0; j < 4; ++j) {
                int col = colBase + warp_n * 32 + j * 8 + cc;
                float v0 = acc[i][j][hf * 2];
                float v1 = acc[i][j][hf * 2 + 1];
                if (EPI == EPI_RESID) {
                    v0 += bias[col];
                    v1 += bias[col + 1];
                    uint32_t rp = resh[((size_t)r * D + col) >> 1];
                    float2 rf = __half22float2(*reinterpret_cast<const __half2*>(&rp));
                    float r0 = rf.x, r1 = rf.y;
                    if (RESBN) {
                        r0 = r0 * t0[col] + t1[col];
                        r1 = r1 * t0[col + 1] + t1[col + 1];
                    }
                    v0 += r0; v1 += r1;
                } else if (EPI == EPI_RELU) {
                    v0 = fmaxf(v0 + bias[col], 0.f);
                    v1 = fmaxf(v1 + bias[col + 1], 0.f);
                }
                if (STATS) {
                    cs[j * 2] += v0;     cq[j * 2] += v0 * v0;
                    cs[j * 2 + 1] += v1; cq[j * 2 + 1] += v1 * v1;
                }
                if (OUTH) {
                    Ch[((size_t)r * ldc + col) >> 1] = pack_h2(v0, v1);
                } else {
                    *(float2*)(Cf + (size_t)r * ldc + col) = make_float2(v0, v1);
                }
            }
        }
    }
    if (STATS) {
#pragma unroll
        for (int t = 0; t < 8; ++t) {
#pragma unroll
            for (int o = 4; o < 32; o <<= 1) {
                cs[t] += __shfl_xor_sync(0xffffffffu, cs[t], o);
                cq[t] += __shfl_xor_sync(0xffffffffu, cq[t], o);
            }
        }
        if (lid < 4) {
#pragma unroll
            for (int t = 0; t < 8; ++t) {
                int col = colBase + warp_n * 32 + (t >> 1) * 8 + lid * 2 + (t & 1);
                atomicAdd(&ssum[col & (D - 1)], cs[t]);
                atomicAdd(&ssq[col & (D - 1)], cq[t]);
            }
        }
    }
}

template <int EPI, bool STATS, bool RESBN, bool OUTH, int KT>
__global__ __launch_bounds__(256, 2) void tgemm_k(
    const __half* __restrict__ A, const __half* __restrict__ W,
    const float* __restrict__ bias, const uint32_t* __restrict__ resh,
    const float* __restrict__ t0, const float* __restrict__ t1,
    float* __restrict__ ssum, float* __restrict__ ssq,
    float* __restrict__ Cf, uint32_t* __restrict__ Ch, int M, int ldc)
{
    tgemm_core<EPI, STATS, RESBN, OUTH, KT>(A, W, bias, resh, t0, t1, ssum, ssq, Cf, Ch,
                                            M, ldc, blockIdx.x * 128, blockIdx.y * 128);
}

__global__ __launch_bounds__(256, 2) void qkv_kernel(int M) {
    int off = (blockIdx.y == 0) ? OFF_WQ : (blockIdx.y == 1) ? OFF_WK : OFF_WV;
    uint32_t* C = (blockIdx.y == 0) ? g_Qh : (blockIdx.y == 1) ? g_Kh : g_Vh;
    tgemm_core<EPI_STORE, false, false, true, 128>(
        (const __half*)g_hh, g_w + off, nullptr, nullptr, nullptr, nullptr,
        nullptr, nullptr, nullptr, C, M, D, blockIdx.x * 128, 0);
}

// ---------------- BN1: fused finalize + convert (fp16 x1 input) ----------------
__global__ __launch_bounds__(256) void bn_convert(
    const uint32_t* __restrict__ x1h, const float* __restrict__ sum,
    const float* __restrict__ sq,
    const float* __restrict__ g, const float* __restrict__ b,
    float* __restrict__ bn_out, int npair, int M)
{
    __shared__ float s_sc[D], s_sh[D];
    int tid = threadIdx.x;
    if (tid < D) {
        float invM = 1.0f / (float)M;
        float mu = sum[tid] * invM;
        float var = sq[tid] * invM - mu * mu;
        float sc = g[tid] * rsqrtf(var + 1e-5f);
        s_sc[tid] = sc;
        s_sh[tid] = b[tid] - mu * sc;
        if (blockIdx.x == 0) {
            bn_out[tid] = sc;
            bn_out[D + tid] = s_sh[tid];
        }
    }
    __syncthreads();
    int p = blockIdx.x * blockDim.x + tid;
    if (p >= npair) return;
    uint32_t rp = x1h[p];
    float2 v = __half22float2(*reinterpret_cast<const __half2*>(&rp));
    int col = (p * 2) & (D - 1);
    g_bx1[p] = pack_h2(v.x * s_sc[col] + s_sh[col], v.y * s_sc[col + 1] + s_sh[col + 1]);
}

// bn_apply with inline BN2 finalize + float4 I/O
__global__ __launch_bounds__(256) void bn_apply(
    const float* __restrict__ x, const float* __restrict__ sum, const float* __restrict__ sq,
    const float* __restrict__ g, const float* __restrict__ b,
    float* __restrict__ out, int M)
{
    __shared__ float s_sc[D], s_sh[D];
    int tid = threadIdx.x;
    if (tid < D) {
        float invM = 1.0f / (float)M;
        float mu = sum[tid] * invM;
        float var = sq[tid] * invM - mu * mu;
        float sc = g[tid] * rsqrtf(var + 1e-5f);
        s_sc[tid] = sc;
        s_sh[tid] = b[tid] - mu * sc;
    }
    __syncthreads();
    int total4 = M * D / 4;
    int stride = gridDim.x * blockDim.x;
    for (int i = blockIdx.x * blockDim.x + tid; i < total4; i += stride) {
        float4 v = ((const float4*)x)[i];
        int col = (i * 4) & (D - 1);
        v.x = v.x * s_sc[col] + s_sh[col];
        v.y = v.y * s_sc[col + 1] + s_sh[col + 1];
        v.z = v.z * s_sc[col + 2] + s_sh[col + 2];
        v.w = v.w * s_sc[col + 3] + s_sh[col + 3];
        ((float4*)out)[i] = v;
    }
}

// ---------------- host launch ----------------
static cudaStream_t g_s1 = nullptr;
static cudaEvent_t g_e0 = nullptr, g_e1 = nullptr;

extern "C" void kernel_launch(void* const* d_in, const int* in_sizes, int n_in,
                              void* d_out, int out_size)
{
    const float* h    = (const float*)d_in[0];
    const int*   src  = (const int*)d_in[1];
    const int*   dst  = (const int*)d_in[2];
    const float* WQ   = (const float*)d_in[3];
    const float* WK   = (const float*)d_in[4];
    const float* WV   = (const float*)d_in[5];
    const float* WO   = (const float*)d_in[6];
    const float* bO   = (const float*)d_in[7];
    const float* W1   = (const float*)d_in[8];
    const float* b1   = (const float*)d_in[9];
    const float* W2   = (const float*)d_in[10];
    const float* b2   = (const float*)d_in[11];
    const float* bn1g = (const float*)d_in[12];
    const float* bn1b = (const float*)d_in[13];
    const float* bn2g = (const float*)d_in[14];
    const float* bn2b = (const float*)d_in[15];
    float* out = (float*)d_out;

    int M = in_sizes[0] / D;
    int E = in_sizes[1];
    if (M > N_NODES) M = N_NODES;
    if (E > N_EDGES) E = N_EDGES;

    float *x2p, *stp, *bn1p;
    uint32_t *attnp, *x1hp, *bx1p, *midp, *hhp;
    __half *wp;
    cudaGetSymbolAddress((void**)&x2p, g_x2);
    cudaGetSymbolAddress((void**)&stp, g_stats);
    cudaGetSymbolAddress((void**)&bn1p, g_bn1);
    cudaGetSymbolAddress((void**)&attnp, g_attn);
    cudaGetSymbolAddress((void**)&x1hp, g_x1h);
    cudaGetSymbolAddress((void**)&bx1p, g_bx1);
    cudaGetSymbolAddress((void**)&midp, g_midh);
    cudaGetSymbolAddress((void**)&hhp, g_hh);
    cudaGetSymbolAddress((void**)&wp, g_w);

    cudaFuncSetAttribute(qkv_kernel, cudaFuncAttributeMaxDynamicSharedMemorySize, DSMEM_BYTES);
    cudaFuncSetAttribute(tgemm_k<EPI_RESID, true, false, true, 128>,
                         cudaFuncAttributeMaxDynamicSharedMemorySize, DSMEM_BYTES);
    cudaFuncSetAttribute(tgemm_k<EPI_RELU, false, false, true, 128>,
                         cudaFuncAttributeMaxDynamicSharedMemorySize, DSMEM_BYTES);
    cudaFuncSetAttribute(tgemm_k<EPI_RESID, true, true, false, 256>,
                         cudaFuncAttributeMaxDynamicSharedMemorySize, DSMEM_BYTES);

    if (g_s1 == nullptr) {
        if (cudaStreamCreateWithFlags(&g_s1, cudaStreamNonBlocking) != cudaSuccess)
            g_s1 = nullptr;
        cudaEventCreateWithFlags(&g_e0, cudaEventDisableTiming);
        cudaEventCreateWithFlags(&g_e1, cudaEventDisableTiming);
    }
    cudaStream_t s1 = g_s1 ? g_s1 : (cudaStream_t)0;

    dim3 blk(256);
    int gx = (M + 127) / 128;
    int nb = (M + 255) / 256;
    int npair = M * D / 2;
    int cvb = (npair + 255) / 256;
    int e4 = (E + 3) / 4;

    // fork: CSR chain on side stream, overlapped with prep + QKV
    cudaEventRecord(g_e0, 0);
    cudaStreamWaitEvent(s1, g_e0, 0);

    zero_cursor<<<nb, 256, 0, s1>>>(M);
    hist_kernel<<<(e4 + 255) / 256, 256, 0, s1>>>(dst, E);
    scan_local<<<nb, 256, 0, s1>>>(M);
    scan_final<<<nb, 256, 0, s1>>>(M, E);
    scatter_kernel<<<(e4 + 255) / 256, 256, 0, s1>>>(src, dst, E);
    cudaEventRecord(g_e1, s1);

    prep_kernel<<<cvb, 256>>>(h, WQ, WK, WV, WO, W1, W2, npair);
    qkv_kernel<<<dim3(gx, 3), blk, DSMEM_BYTES>>>(M);

    cudaStreamWaitEvent(0, g_e1, 0);

    gather_kernel<<<(M * 32 + 255) / 256, 256>>>(M);

    // O projection: attn @ WO^T + bO + h(fp16) -> x1 fp16 (+ BN1 stats)
    tgemm_k<EPI_RESID, true, false, true, 128><<<dim3(gx, 1), blk, DSMEM_BYTES>>>(
        (const __half*)attnp, wp + OFF_WO, bO, hhp, nullptr, nullptr,
        stp, stp + D, nullptr, x1hp, M, D);

    bn_convert<<<cvb, 256>>>(x1hp, stp, stp + D, bn1g, bn1b, bn1p, npair, M);

    // FFN1: relu(BN1(x1) @ W1^T + b1) -> mid fp16 [N, 256]
    tgemm_k<EPI_RELU, false, false, true, 128><<<dim3(gx, 2), blk, DSMEM_BYTES>>>(
        (const __half*)bx1p, wp + OFF_W1, b1, nullptr, nullptr, nullptr,
        nullptr, nullptr, nullptr, midp, M, 2 * D);

    // FFN2: mid @ W2^T + b2 + BN1(x1 fp16) -> x2 fp32 (+ BN2 stats)
    tgemm_k<EPI_RESID, true, true, false, 256><<<dim3(gx, 1), blk, DSMEM_BYTES>>>(
        (const __half*)midp, wp + OFF_W2, b2, x1hp, bn1p, bn1p + D,
        stp + 2 * D, stp + 3 * D, x2p, nullptr, M, D);

    bn_apply<<<1024, 256>>>(x2p, stp + 2 * D, stp + 3 * D, bn2g, bn2b, out, M);
}

// round 17
// speedup vs baseline: 1.7727x; 1.0675x over previous
#include <cuda_runtime.h>
#include <cuda_fp16.h>
#include <math.h>
#include <stdint.h>

#define N_NODES 50000
#define N_EDGES 640000
#define D 128
#define H 8

// ---------------- scratch (static device globals; no allocation) ----------------
__device__ float g_x2[N_NODES * D];
__device__ float g_stats[4 * D];
__device__ float g_bn1[2 * D];
// fp16x2-packed buffers
__device__ uint32_t g_Qh [N_NODES * D / 2];
__device__ uint32_t g_Kh [N_NODES * D / 2];
__device__ uint32_t g_Vh [N_NODES * D / 2];
__device__ uint32_t g_attn[N_NODES * D / 2];
__device__ uint32_t g_hh [N_NODES * D / 2];
__device__ uint32_t g_x1h[N_NODES * D / 2];
__device__ uint32_t g_bx1[N_NODES * D / 2];
// CSR
__device__ int g_rowptr[N_NODES + 1];
__device__ int g_cursor[N_NODES];
__device__ int g_csrc[N_EDGES];
__device__ int g_part[256];
// pre-converted weights (fp16)
#define W_TOTAL 131072
__device__ __half g_w[W_TOTAL];
#define OFF_WQ 0
#define OFF_WK 16384
#define OFF_WV 32768
#define OFF_WO 49152
#define OFF_W1 65536
#define OFF_W2 98304

// ---------------- helpers ----------------
__device__ __forceinline__ uint32_t smem_u32(const void* p) {
    uint32_t a;
    asm("{ .reg .u64 t; cvta.to.shared.u64 t, %1; cvt.u32.u64 %0, t; }" : "=r"(a) : "l"(p));
    return a;
}
__device__ __forceinline__ void ldm_x4(uint32_t& a0, uint32_t& a1, uint32_t& a2, uint32_t& a3,
                                       uint32_t addr) {
    asm volatile("ldmatrix.sync.aligned.m8n8.x4.shared.b16 {%0,%1,%2,%3}, [%4];"
                 : "=r"(a0), "=r"(a1), "=r"(a2), "=r"(a3) : "r"(addr));
}
__device__ __forceinline__ void ldm_x2(uint32_t& b0, uint32_t& b1, uint32_t addr) {
    asm volatile("ldmatrix.sync.aligned.m8n8.x2.shared.b16 {%0,%1}, [%2];"
                 : "=r"(b0), "=r"(b1) : "r"(addr));
}
__device__ __forceinline__ void mma_f16(float* c, uint32_t a0, uint32_t a1, uint32_t a2,
                                        uint32_t a3, uint32_t b0, uint32_t b1) {
    asm volatile(
        "mma.sync.aligned.m16n8k16.row.col.f32.f16.f16.f32 "
        "{%0,%1,%2,%3}, {%4,%5,%6,%7}, {%8,%9}, {%0,%1,%2,%3};"
        : "+f"(c[0]), "+f"(c[1]), "+f"(c[2]), "+f"(c[3])
        : "r"(a0), "r"(a1), "r"(a2), "r"(a3), "r"(b0), "r"(b1));
}
__device__ __forceinline__ uint32_t pack_h2(float a, float b) {
    uint32_t r;
    asm("cvt.rn.f16x2.f32 %0, %1, %2;" : "=r"(r) : "f"(b), "f"(a));
    return r;
}
__device__ __forceinline__ void cp16(uint32_t dst, const void* src) {
    asm volatile("cp.async.cg.shared.global [%0], [%1], 16;" :: "r"(dst), "l"(src));
}
__device__ __forceinline__ void cp16ca(uint32_t dst, const void* src) {
    asm volatile("cp.async.ca.shared.global [%0], [%1], 16;" :: "r"(dst), "l"(src));
}
__device__ __forceinline__ void cp16z(uint32_t dst, const void* src, bool pred) {
    int sz = pred ? 16 : 0;
    asm volatile("cp.async.cg.shared.global [%0], [%1], 16, %2;"
                 :: "r"(dst), "l"(src), "r"(sz));
}
#define CP_COMMIT() asm volatile("cp.async.commit_group;" ::: "memory")
#define CP_WAIT0()  asm volatile("cp.async.wait_group 0;" ::: "memory")
#define CP_WAIT1()  asm volatile("cp.async.wait_group 1;" ::: "memory")

// ---------------- fused prep ----------------
__global__ void prep_kernel(const float* __restrict__ h,
                            const float* __restrict__ WQ, const float* __restrict__ WK,
                            const float* __restrict__ WV, const float* __restrict__ WO,
                            const float* __restrict__ W1, const float* __restrict__ W2,
                            int npair)
{
    int gid = blockIdx.x * blockDim.x + threadIdx.x;
    if (gid < npair) {
        float2 v = ((const float2*)h)[gid];
        g_hh[gid] = pack_h2(v.x, v.y);
    }
    if (gid < W_TOTAL / 2) {
        int elem = gid * 2;
        const float* src;
        int local;
        if (elem < OFF_W1) {
            int m = elem >> 14;
            local = elem & 16383;
            src = (m == 0) ? WQ : (m == 1) ? WK : (m == 2) ? WV : WO;
        } else if (elem < OFF_W2) {
            local = elem - OFF_W1;
            src = W1;
        } else {
            local = elem - OFF_W2;
            src = W2;
        }
        ((uint32_t*)g_w)[gid] = pack_h2(src[local], src[local + 1]);
    }
    if (gid < 4 * D) g_stats[gid] = 0.f;
}

// ---------------- CSR build (side stream) ----------------
__global__ void zero_cursor(int n) {
    int i = blockIdx.x * blockDim.x + threadIdx.x;
    if (i < n) g_cursor[i] = 0;
}

__global__ void hist_kernel(const int* __restrict__ dst, int E) {
    int q = blockIdx.x * blockDim.x + threadIdx.x;
    int e = q * 4;
    if (e + 4 <= E) {
        int4 d4 = *(const int4*)(dst + e);
        atomicAdd(&g_cursor[d4.x], 1);
        atomicAdd(&g_cursor[d4.y], 1);
        atomicAdd(&g_cursor[d4.z], 1);
        atomicAdd(&g_cursor[d4.w], 1);
    } else {
        for (int i = e; i < E; ++i) atomicAdd(&g_cursor[dst[i]], 1);
    }
}

__global__ __launch_bounds__(256) void scan_local(int n) {
    int tid = threadIdx.x;
    int lane = tid & 31;
    int wid = tid >> 5;
    int i = blockIdx.x * 256 + tid;
    int c = (i < n) ? g_cursor[i] : 0;
    int v = c;
#pragma unroll
    for (int o = 1; o < 32; o <<= 1) {
        int t = __shfl_up_sync(0xffffffffu, v, o);
        if (lane >= o) v += t;
    }
    __shared__ int wsum[8];
    if (lane == 31) wsum[wid] = v;
    __syncthreads();
    if (wid == 0 && lane < 8) {
        int w = wsum[lane];
#pragma unroll
        for (int o = 1; o < 8; o <<= 1) {
            int t = __shfl_up_sync(0xffu, w, o);
            if (lane >= o) w += t;
        }
        wsum[lane] = w;
    }
    __syncthreads();
    int off = (wid > 0) ? wsum[wid - 1] : 0;
    if (i < n) g_rowptr[i] = v - c + off;
    if (tid == 255) g_part[blockIdx.x] = v + off;
}

__global__ __launch_bounds__(256) void scan_final(int n, int E) {
    int tid = threadIdx.x;
    int lane = tid & 31;
    int wid = tid >> 5;
    int nb = gridDim.x;
    int p = (tid < nb && tid < (int)blockIdx.x) ? g_part[tid] : 0;
#pragma unroll
    for (int o = 16; o > 0; o >>= 1) p += __shfl_xor_sync(0xffffffffu, p, o);
    __shared__ int wsum[8];
    __shared__ int s_off;
    if (lane == 0) wsum[wid] = p;
    __syncthreads();
    if (tid == 0) {
        int s = 0;
#pragma unroll
        for (int w = 0; w < 8; ++w) s += wsum[w];
        s_off = s;
    }
    __syncthreads();
    int i = blockIdx.x * 256 + tid;
    if (i < n) {
        int r = g_rowptr[i] + s_off;
        g_rowptr[i] = r;
        g_cursor[i] = r;
    }
    if (i == 0) g_rowptr[n] = E;
}

__global__ void scatter_kernel(const int* __restrict__ src, const int* __restrict__ dst, int E) {
    int q = blockIdx.x * blockDim.x + threadIdx.x;
    int e = q * 4;
    if (e + 4 <= E) {
        int4 s4 = *(const int4*)(src + e);
        int4 d4 = *(const int4*)(dst + e);
        g_csrc[atomicAdd(&g_cursor[d4.x], 1)] = s4.x;
        g_csrc[atomicAdd(&g_cursor[d4.y], 1)] = s4.y;
        g_csrc[atomicAdd(&g_cursor[d4.z], 1)] = s4.z;
        g_csrc[atomicAdd(&g_cursor[d4.w], 1)] = s4.w;
    } else {
        for (int i = e; i < E; ++i)
            g_csrc[atomicAdd(&g_cursor[dst[i]], 1)] = src[i];
    }
}

// ---------------- gather attention: fp16 K/V, warp per node, 4-wide unroll ------
__device__ __forceinline__ float4 unp4(uint2 u) {
    float2 a = __half22float2(*reinterpret_cast<const __half2*>(&u.x));
    float2 b = __half22float2(*reinterpret_cast<const __half2*>(&u.y));
    return make_float4(a.x, a.y, b.x, b.y);
}

__global__ __launch_bounds__(256) void gather_kernel(int n) {
    int warp = (blockIdx.x * blockDim.x + threadIdx.x) >> 5;
    if (warp >= n) return;
    const int lid = threadIdx.x & 31;
    const int d = warp;
    const size_t base = (size_t)d * (D / 2) + lid * 2;

    float4 q = unp4(*(const uint2*)(g_Qh + base));
    float4 acc = make_float4(0.f, 0.f, 0.f, 0.f);
    float zacc = 0.f;

    int beg = g_rowptr[d], end = g_rowptr[d + 1];
    int i = beg;
    for (; i + 4 <= end; i += 4) {
        int s0 = g_csrc[i], s1 = g_csrc[i + 1], s2 = g_csrc[i + 2], s3 = g_csrc[i + 3];
        size_t o0 = (size_t)s0 * (D / 2) + lid * 2;
        size_t o1 = (size_t)s1 * (D / 2) + lid * 2;
        size_t o2 = (size_t)s2 * (D / 2) + lid * 2;
        size_t o3 = (size_t)s3 * (D / 2) + lid * 2;
        float4 k0 = unp4(*(const uint2*)(g_Kh + o0));
        float4 k1 = unp4(*(const uint2*)(g_Kh + o1));
        float4 k2 = unp4(*(const uint2*)(g_Kh + o2));
        float4 k3 = unp4(*(const uint2*)(g_Kh + o3));
        float4 v0 = unp4(*(const uint2*)(g_Vh + o0));
        float4 v1 = unp4(*(const uint2*)(g_Vh + o1));
        float4 v2 = unp4(*(const uint2*)(g_Vh + o2));
        float4 v3 = unp4(*(const uint2*)(g_Vh + o3));
        float p0 = q.x * k0.x + q.y * k0.y + q.z * k0.z + q.w * k0.w;
        float p1 = q.x * k1.x + q.y * k1.y + q.z * k1.z + q.w * k1.w;
        float p2 = q.x * k2.x + q.y * k2.y + q.z * k2.z + q.w * k2.w;
        float p3 = q.x * k3.x + q.y * k3.y + q.z * k3.z + q.w * k3.w;
        p0 += __shfl_xor_sync(0xffffffffu, p0, 1);
        p1 += __shfl_xor_sync(0xffffffffu, p1, 1);
        p2 += __shfl_xor_sync(0xffffffffu, p2, 1);
        p3 += __shfl_xor_sync(0xffffffffu, p3, 1);
        p0 += __shfl_xor_sync(0xffffffffu, p0, 2);
        p1 += __shfl_xor_sync(0xffffffffu, p1, 2);
        p2 += __shfl_xor_sync(0xffffffffu, p2, 2);
        p3 += __shfl_xor_sync(0xffffffffu, p3, 2);
        float sc0 = __expf(fminf(fmaxf(p0 * 0.25f, -5.f), 5.f));
        float sc1 = __expf(fminf(fmaxf(p1 * 0.25f, -5.f), 5.f));
        float sc2 = __expf(fminf(fmaxf(p2 * 0.25f, -5.f), 5.f));
        float sc3 = __expf(fminf(fmaxf(p3 * 0.25f, -5.f), 5.f));
        acc.x += v0.x * sc0 + v1.x * sc1 + v2.x * sc2 + v3.x * sc3;
        acc.y += v0.y * sc0 + v1.y * sc1 + v2.y * sc2 + v3.y * sc3;
        acc.z += v0.z * sc0 + v1.z * sc1 + v2.z * sc2 + v3.z * sc3;
        acc.w += v0.w * sc0 + v1.w * sc1 + v2.w * sc2 + v3.w * sc3;
        zacc += (sc0 + sc1) + (sc2 + sc3);
    }
    for (; i < end; ++i) {
        int s0 = g_csrc[i];
        size_t o0 = (size_t)s0 * (D / 2) + lid * 2;
        float4 k0 = unp4(*(const uint2*)(g_Kh + o0));
        float4 v0 = unp4(*(const uint2*)(g_Vh + o0));
        float p0 = q.x * k0.x + q.y * k0.y + q.z * k0.z + q.w * k0.w;
        p0 += __shfl_xor_sync(0xffffffffu, p0, 1);
        p0 += __shfl_xor_sync(0xffffffffu, p0, 2);
        float sc0 = __expf(fminf(fmaxf(p0 * 0.25f, -5.f), 5.f));
        acc.x += v0.x * sc0; acc.y += v0.y * sc0;
        acc.z += v0.z * sc0; acc.w += v0.w * sc0;
        zacc += sc0;
    }
    float inv = 1.0f / zacc;
    *(uint2*)(g_attn + base) = make_uint2(pack_h2(acc.x * inv, acc.y * inv),
                                          pack_h2(acc.z * inv, acc.w * inv));
}

// ---------------- shared GEMM fragment geometry ----------------
enum { EPI_STORE = 0, EPI_RESID = 1 };

#define BK 64
#define SK 72
#define TILEB (128 * SK * 2)
#define STAGE_B (2 * TILEB)
#define DSMEM_BYTES (2 * STAGE_B)

// ---------------- generic GEMM (QKV / O-proj) ----------------
template <int EPI, bool STATS, bool OUTH, int KT>
__device__ __forceinline__ void tgemm_core(
    const __half* __restrict__ A, const __half* __restrict__ W,
    const float* __restrict__ bias, const uint32_t* __restrict__ resh,
    float* __restrict__ ssum, float* __restrict__ ssq,
    float* __restrict__ Cf, uint32_t* __restrict__ Ch,
    int M, int ldc, int rowBase, int colBase)
{
    extern __shared__ __align__(16) char sm[];
    const uint32_t smbase = smem_u32(sm);

    const int tid = threadIdx.x;
    const int wid = tid >> 5;
    const int lid = tid & 31;
    const int warp_m = wid & 1;
    const int warp_n = wid >> 1;

    const int ar = (lid & 7) + ((lid >> 3) & 1) * 8;
    const int ac = (lid >> 4) * 8;
    const int br = lid & 7;
    const int bc = ((lid >> 3) & 1) * 8;

    const uint32_t aOff = (uint32_t)((warp_m * 64 + ar) * SK + ac) * 2;
    const uint32_t bOff = (uint32_t)((warp_n * 32 + br) * SK + bc) * 2;

    float acc[4][4][4];
#pragma unroll
    for (int i = 0; i < 4; ++i)
#pragma unroll
        for (int j = 0; j < 4; ++j)
#pragma unroll
            for (int t = 0; t < 4; ++t) acc[i][j][t] = 0.f;

    const int row = tid >> 1;
    const int kh = (tid & 1) * 32;
    const int grow = rowBase + row;
    const bool valid = grow < M;

    const __half* pA = A + (size_t)grow * KT + kh;
    const __half* pW = W + (size_t)(colBase + row) * KT + kh;
    const uint32_t sdst = (uint32_t)(row * SK + kh) * 2;

    auto load_slab = [&](int slab, int stage) {
        uint32_t sb = smbase + stage * STAGE_B + sdst;
        const __half* a = pA + slab * BK;
        const __half* w = pW + slab * BK;
#pragma unroll
        for (int c = 0; c < 4; ++c) cp16z(sb + c * 16, a + c * 8, valid);
#pragma unroll
        for (int c = 0; c < 4; ++c) cp16ca(sb + TILEB + c * 16, w + c * 8);
        CP_COMMIT();
    };

    constexpr int NSLAB = KT / BK;
    load_slab(0, 0);
#pragma unroll
    for (int s = 0; s < NSLAB; ++s) {
        if (s + 1 < NSLAB) {
            load_slab(s + 1, (s + 1) & 1);
            CP_WAIT1();
        } else {
            CP_WAIT0();
        }
        __syncthreads();

        const uint32_t stA = smbase + (s & 1) * STAGE_B;
        const uint32_t stW = stA + TILEB;
#pragma unroll
        for (int ks = 0; ks < 4; ++ks) {
            const uint32_t k0 = (uint32_t)(ks * 16) * 2;
            uint32_t bh[4][2];
#pragma unroll
            for (int j = 0; j < 4; ++j)
                ldm_x2(bh[j][0], bh[j][1], stW + bOff + (uint32_t)(j * 8 * SK) * 2 + k0);
#pragma unroll
            for (int i = 0; i < 4; ++i) {
                uint32_t a0, a1, a2, a3;
                ldm_x4(a0, a1, a2, a3, stA + aOff + (uint32_t)(i * 16 * SK) * 2 + k0);
#pragma unroll
                for (int j = 0; j < 4; ++j)
                    mma_f16(acc[i][j], a0, a1, a2, a3, bh[j][0], bh[j][1]);
            }
        }
        if (s + 2 < NSLAB) __syncthreads();
    }

    const int rr = lid >> 2;
    const int cc = (lid & 3) * 2;
    float cs[8], cq[8];
    if (STATS) {
#pragma unroll
        for (int t = 0; t < 8; ++t) { cs[t] = 0.f; cq[t] = 0.f; }
    }
#pragma unroll
    for (int i = 0; i < 4; ++i) {
#pragma unroll
        for (int hf = 0; hf < 2; ++hf) {
            int r = rowBase + warp_m * 64 + i * 16 + rr + hf * 8;
            if (r >= M) continue;
#pragma unroll
            for (int j = 0; j < 4; ++j) {
                int col = colBase + warp_n * 32 + j * 8 + cc;
                float v0 = acc[i][j][hf * 2];
                float v1 = acc[i][j][hf * 2 + 1];
                if (EPI == EPI_RESID) {
                    v0 += bias[col];
                    v1 += bias[col + 1];
                    uint32_t rp = resh[((size_t)r * D + col) >> 1];
                    float2 rf = __half22float2(*reinterpret_cast<const __half2*>(&rp));
                    v0 += rf.x; v1 += rf.y;
                }
                if (STATS) {
                    cs[j * 2] += v0;     cq[j * 2] += v0 * v0;
                    cs[j * 2 + 1] += v1; cq[j * 2 + 1] += v1 * v1;
                }
                if (OUTH) {
                    Ch[((size_t)r * ldc + col) >> 1] = pack_h2(v0, v1);
                } else {
                    *(float2*)(Cf + (size_t)r * ldc + col) = make_float2(v0, v1);
                }
            }
        }
    }
    if (STATS) {
#pragma unroll
        for (int t = 0; t < 8; ++t) {
#pragma unroll
            for (int o = 4; o < 32; o <<= 1) {
                cs[t] += __shfl_xor_sync(0xffffffffu, cs[t], o);
                cq[t] += __shfl_xor_sync(0xffffffffu, cq[t], o);
            }
        }
        if (lid < 4) {
#pragma unroll
            for (int t = 0; t < 8; ++t) {
                int col = colBase + warp_n * 32 + (t >> 1) * 8 + lid * 2 + (t & 1);
                atomicAdd(&ssum[col & (D - 1)], cs[t]);
                atomicAdd(&ssq[col & (D - 1)], cq[t]);
            }
        }
    }
}

template <int EPI, bool STATS, bool OUTH, int KT>
__global__ __launch_bounds__(256, 2) void tgemm_k(
    const __half* __restrict__ A, const __half* __restrict__ W,
    const float* __restrict__ bias, const uint32_t* __restrict__ resh,
    float* __restrict__ ssum, float* __restrict__ ssq,
    float* __restrict__ Cf, uint32_t* __restrict__ Ch, int M, int ldc)
{
    tgemm_core<EPI, STATS, OUTH, KT>(A, W, bias, resh, ssum, ssq, Cf, Ch,
                                     M, ldc, blockIdx.x * 128, blockIdx.y * 128);
}

__global__ __launch_bounds__(256, 2) void qkv_kernel(int M) {
    int off = (blockIdx.y == 0) ? OFF_WQ : (blockIdx.y == 1) ? OFF_WK : OFF_WV;
    uint32_t* C = (blockIdx.y == 0) ? g_Qh : (blockIdx.y == 1) ? g_Kh : g_Vh;
    tgemm_core<EPI_STORE, false, true, 128>(
        (const __half*)g_hh, g_w + off, nullptr, nullptr,
        nullptr, nullptr, nullptr, C, M, D, blockIdx.x * 128, 0);
}

// ---------------- fused FFN: mid = relu(bx1@W1^T+b1) in smem, x2 = mid@W2^T+b2+bx1
// smem: [Ast0 Ast1 | Wst0 Wst1 | mid0 mid1 mid2 mid3]  = 8*TILEB = 147456 B
#define DSMEM_FFN (8 * TILEB)

__global__ __launch_bounds__(256, 1) void ffn_kernel(
    const float* __restrict__ b1, const float* __restrict__ b2,
    float* __restrict__ ssum, float* __restrict__ ssq,
    float* __restrict__ x2, int M)
{
    extern __shared__ __align__(16) char sm[];
    const uint32_t smbase = smem_u32(sm);
    const uint32_t wstBase = smbase + 2 * TILEB;
    const uint32_t midBase = smbase + 4 * TILEB;

    const int tid = threadIdx.x;
    const int wid = tid >> 5;
    const int lid = tid & 31;
    const int warp_m = wid & 1;
    const int warp_n = wid >> 1;
    const int rowBase = blockIdx.x * 128;

    const int ar = (lid & 7) + ((lid >> 3) & 1) * 8;
    const int ac = (lid >> 4) * 8;
    const int br = lid & 7;
    const int bc = ((lid >> 3) & 1) * 8;
    const uint32_t aOff = (uint32_t)((warp_m * 64 + ar) * SK + ac) * 2;
    const uint32_t bOff = (uint32_t)((warp_n * 32 + br) * SK + bc) * 2;

    const int row = tid >> 1;
    const int kh = (tid & 1) * 32;
    const int grow = rowBase + row;
    const bool valid = grow < M;
    const uint32_t sdst = (uint32_t)(row * SK + kh) * 2;

    const __half* pA = (const __half*)g_bx1 + (size_t)grow * D + kh;      // bx1 K=128
    const __half* W1h = g_w + OFF_W1;                                      // 256 x 128
    const __half* W2h = g_w + OFF_W2;                                      // 128 x 256

    const int rr = lid >> 2;
    const int cc = (lid & 3) * 2;

    float acc[4][4][4];

    // ---- prologue: A slabs (bx1) + W1 half0 slabs ----
#pragma unroll
    for (int s = 0; s < 2; ++s) {
        const __half* a = pA + s * BK;
        uint32_t ab = smbase + s * TILEB + sdst;
#pragma unroll
        for (int c = 0; c < 4; ++c) cp16z(ab + c * 16, a + c * 8, valid);
        const __half* w = W1h + (size_t)row * 128 + kh + s * BK;
        uint32_t wb = wstBase + s * TILEB + sdst;
#pragma unroll
        for (int c = 0; c < 4; ++c) cp16ca(wb + c * 16, w + c * 8);
    }
    CP_COMMIT();
    CP_WAIT0();
    __syncthreads();

    // ---- FFN1 halves ----
#pragma unroll
    for (int half = 0; half < 2; ++half) {
#pragma unroll
        for (int i = 0; i < 4; ++i)
#pragma unroll
            for (int j = 0; j < 4; ++j)
#pragma unroll
                for (int t = 0; t < 4; ++t) acc[i][j][t] = 0.f;

#pragma unroll
        for (int s = 0; s < 2; ++s) {
            const uint32_t stA = smbase + s * TILEB;
            const uint32_t stW = wstBase + s * TILEB;
#pragma unroll
            for (int ks = 0; ks < 4; ++ks) {
                const uint32_t k0 = (uint32_t)(ks * 16) * 2;
                uint32_t bh[4][2];
#pragma unroll
                for (int j = 0; j < 4; ++j)
                    ldm_x2(bh[j][0], bh[j][1], stW + bOff + (uint32_t)(j * 8 * SK) * 2 + k0);
#pragma unroll
                for (int i = 0; i < 4; ++i) {
                    uint32_t a0, a1, a2, a3;
                    ldm_x4(a0, a1, a2, a3, stA + aOff + (uint32_t)(i * 16 * SK) * 2 + k0);
#pragma unroll
                    for (int j = 0; j < 4; ++j)
                        mma_f16(acc[i][j], a0, a1, a2, a3, bh[j][0], bh[j][1]);
                }
            }
        }
        __syncthreads();   // all reads of Wst done before refill

        // prefetch next phase's W while epilogue runs
        if (half == 0) {
#pragma unroll
            for (int s = 0; s < 2; ++s) {
                const __half* w = W1h + (size_t)(128 + row) * 128 + kh + s * BK;
                uint32_t wb = wstBase + s * TILEB + sdst;
#pragma unroll
                for (int c = 0; c < 4; ++c) cp16ca(wb + c * 16, w + c * 8);
            }
            CP_COMMIT();
        } else {
            const __half* w = W2h + (size_t)row * 256 + kh;   // W2 slab 0
            uint32_t wb = wstBase + sdst;
#pragma unroll
            for (int c = 0; c < 4; ++c) cp16ca(wb + c * 16, w + c * 8);
            CP_COMMIT();
        }

        // epilogue: relu -> mid smem slabs (half*2 + col/64)
#pragma unroll
        for (int i = 0; i < 4; ++i) {
#pragma unroll
            for (int hf = 0; hf < 2; ++hf) {
                int rl = warp_m * 64 + i * 16 + rr + hf * 8;
#pragma unroll
                for (int j = 0; j < 4; ++j) {
                    int col = warp_n * 32 + j * 8 + cc;
                    float v0 = fmaxf(acc[i][j][hf * 2] + b1[half * 128 + col], 0.f);
                    float v1 = fmaxf(acc[i][j][hf * 2 + 1] + b1[half * 128 + col + 1], 0.f);
                    int sl = half * 2 + (col >> 6);
                    *(uint32_t*)(sm + (size_t)(4 + sl) * TILEB
                                 + ((size_t)rl * SK + (col & 63)) * 2) = pack_h2(v0, v1);
                }
            }
        }
        CP_WAIT0();
        __syncthreads();
    }

    // ---- FFN2: A = mid (smem), W2 streamed 2-stage over 4 slabs ----
#pragma unroll
    for (int i = 0; i < 4; ++i)
#pragma unroll
        for (int j = 0; j < 4; ++j)
#pragma unroll
            for (int t = 0; t < 4; ++t) acc[i][j][t] = 0.f;

#pragma unroll
    for (int s = 0; s < 4; ++s) {
        if (s + 1 < 4) {
            const __half* w = W2h + (size_t)row * 256 + kh + (s + 1) * BK;
            uint32_t wb = wstBase + ((s + 1) & 1) * TILEB + sdst;
#pragma unroll
            for (int c = 0; c < 4; ++c) cp16ca(wb + c * 16, w + c * 8);
            CP_COMMIT();
            CP_WAIT1();
        } else {
            CP_WAIT0();
        }
        __syncthreads();

        const uint32_t stA = midBase + s * TILEB;
        const uint32_t stW = wstBase + (s & 1) * TILEB;
#pragma unroll
        for (int ks = 0; ks < 4; ++ks) {
            const uint32_t k0 = (uint32_t)(ks * 16) * 2;
            uint32_t bh[4][2];
#pragma unroll
            for (int j = 0; j < 4; ++j)
                ldm_x2(bh[j][0], bh[j][1], stW + bOff + (uint32_t)(j * 8 * SK) * 2 + k0);
#pragma unroll
            for (int i = 0; i < 4; ++i) {
                uint32_t a0, a1, a2, a3;
                ldm_x4(a0, a1, a2, a3, stA + aOff + (uint32_t)(i * 16 * SK) * 2 + k0);
#pragma unroll
                for (int j = 0; j < 4; ++j)
                    mma_f16(acc[i][j], a0, a1, a2, a3, bh[j][0], bh[j][1]);
            }
        }
        if (s + 2 < 4) __syncthreads();
    }

    // ---- epilogue: + b2 + resid(bx1 from A stages) + BN2 stats, store fp32 ----
    float cs[8], cq[8];
#pragma unroll
    for (int t = 0; t < 8; ++t) { cs[t] = 0.f; cq[t] = 0.f; }
#pragma unroll
    for (int i = 0; i < 4; ++i) {
#pragma unroll
        for (int hf = 0; hf < 2; ++hf) {
            int rl = warp_m * 64 + i * 16 + rr + hf * 8;
            int r = rowBase + rl;
            if (r >= M) continue;
#pragma unroll
            for (int j = 0; j < 4; ++j) {
                int col = warp_n * 32 + j * 8 + cc;
                int sl = col >> 6;
                uint32_t rp = *(const uint32_t*)(sm + (size_t)sl * TILEB
                              + ((size_t)rl * SK + (col & 63)) * 2);
                float2 rf = __half22float2(*reinterpret_cast<const __half2*>(&rp));
                float v0 = acc[i][j][hf * 2] + b2[col] + rf.x;
                float v1 = acc[i][j][hf * 2 + 1] + b2[col + 1] + rf.y;
                cs[j * 2] += v0;     cq[j * 2] += v0 * v0;
                cs[j * 2 + 1] += v1; cq[j * 2 + 1] += v1 * v1;
                *(float2*)(x2 + (size_t)r * D + col) = make_float2(v0, v1);
            }
        }
    }
#pragma unroll
    for (int t = 0; t < 8; ++t) {
#pragma unroll
        for (int o = 4; o < 32; o <<= 1) {
            cs[t] += __shfl_xor_sync(0xffffffffu, cs[t], o);
            cq[t] += __shfl_xor_sync(0xffffffffu, cq[t], o);
        }
    }
    if (lid < 4) {
#pragma unroll
        for (int t = 0; t < 8; ++t) {
            int col = warp_n * 32 + (t >> 1) * 8 + lid * 2 + (t & 1);
            atomicAdd(&ssum[col], cs[t]);
            atomicAdd(&ssq[col], cq[t]);
        }
    }
}

// ---------------- BN1: fused finalize + convert (fp16 x1 input) ----------------
__global__ __launch_bounds__(256) void bn_convert(
    const uint32_t* __restrict__ x1h, const float* __restrict__ sum,
    const float* __restrict__ sq,
    const float* __restrict__ g, const float* __restrict__ b,
    int npair, int M)
{
    __shared__ float s_sc[D], s_sh[D];
    int tid = threadIdx.x;
    if (tid < D) {
        float invM = 1.0f / (float)M;
        float mu = sum[tid] * invM;
        float var = sq[tid] * invM - mu * mu;
        float sc = g[tid] * rsqrtf(var + 1e-5f);
        s_sc[tid] = sc;
        s_sh[tid] = b[tid] - mu * sc;
    }
    __syncthreads();
    int p = blockIdx.x * blockDim.x + tid;
    if (p >= npair) return;
    uint32_t rp = x1h[p];
    float2 v = __half22float2(*reinterpret_cast<const __half2*>(&rp));
    int col = (p * 2) & (D - 1);
    g_bx1[p] = pack_h2(v.x * s_sc[col] + s_sh[col], v.y * s_sc[col + 1] + s_sh[col + 1]);
}

// bn_apply with inline BN2 finalize + float4 I/O
__global__ __launch_bounds__(256) void bn_apply(
    const float* __restrict__ x, const float* __restrict__ sum, const float* __restrict__ sq,
    const float* __restrict__ g, const float* __restrict__ b,
    float* __restrict__ out, int M)
{
    __shared__ float s_sc[D], s_sh[D];
    int tid = threadIdx.x;
    if (tid < D) {
        float invM = 1.0f / (float)M;
        float mu = sum[tid] * invM;
        float var = sq[tid] * invM - mu * mu;
        float sc = g[tid] * rsqrtf(var + 1e-5f);
        s_sc[tid] = sc;
        s_sh[tid] = b[tid] - mu * sc;
    }
    __syncthreads();
    int total4 = M * D / 4;
    int stride = gridDim.x * blockDim.x;
    for (int i = blockIdx.x * blockDim.x + tid; i < total4; i += stride) {
        float4 v = ((const float4*)x)[i];
        int col = (i * 4) & (D - 1);
        v.x = v.x * s_sc[col] + s_sh[col];
        v.y = v.y * s_sc[col + 1] + s_sh[col + 1];
        v.z = v.z * s_sc[col + 2] + s_sh[col + 2];
        v.w = v.w * s_sc[col + 3] + s_sh[col + 3];
        ((float4*)out)[i] = v;
    }
}

// ---------------- host launch ----------------
static cudaStream_t g_s1 = nullptr;
static cudaEvent_t g_e0 = nullptr, g_e1 = nullptr;

extern "C" void kernel_launch(void* const* d_in, const int* in_sizes, int n_in,
                              void* d_out, int out_size)
{
    const float* h    = (const float*)d_in[0];
    const int*   src  = (const int*)d_in[1];
    const int*   dst  = (const int*)d_in[2];
    const float* WQ   = (const float*)d_in[3];
    const float* WK   = (const float*)d_in[4];
    const float* WV   = (const float*)d_in[5];
    const float* WO   = (const float*)d_in[6];
    const float* bO   = (const float*)d_in[7];
    const float* W1   = (const float*)d_in[8];
    const float* b1   = (const float*)d_in[9];
    const float* W2   = (const float*)d_in[10];
    const float* b2   = (const float*)d_in[11];
    const float* bn1g = (const float*)d_in[12];
    const float* bn1b = (const float*)d_in[13];
    const float* bn2g = (const float*)d_in[14];
    const float* bn2b = (const float*)d_in[15];
    float* out = (float*)d_out;

    int M = in_sizes[0] / D;
    int E = in_sizes[1];
    if (M > N_NODES) M = N_NODES;
    if (E > N_EDGES) E = N_EDGES;

    float *x2p, *stp;
    uint32_t *attnp, *x1hp, *hhp;
    __half *wp;
    cudaGetSymbolAddress((void**)&x2p, g_x2);
    cudaGetSymbolAddress((void**)&stp, g_stats);
    cudaGetSymbolAddress((void**)&attnp, g_attn);
    cudaGetSymbolAddress((void**)&x1hp, g_x1h);
    cudaGetSymbolAddress((void**)&hhp, g_hh);
    cudaGetSymbolAddress((void**)&wp, g_w);

    cudaFuncSetAttribute(qkv_kernel, cudaFuncAttributeMaxDynamicSharedMemorySize, DSMEM_BYTES);
    cudaFuncSetAttribute(tgemm_k<EPI_RESID, true, true, 128>,
                         cudaFuncAttributeMaxDynamicSharedMemorySize, DSMEM_BYTES);
    cudaFuncSetAttribute(ffn_kernel, cudaFuncAttributeMaxDynamicSharedMemorySize, DSMEM_FFN);

    if (g_s1 == nullptr) {
        if (cudaStreamCreateWithFlags(&g_s1, cudaStreamNonBlocking) != cudaSuccess)
            g_s1 = nullptr;
        cudaEventCreateWithFlags(&g_e0, cudaEventDisableTiming);
        cudaEventCreateWithFlags(&g_e1, cudaEventDisableTiming);
    }
    cudaStream_t s1 = g_s1 ? g_s1 : (cudaStream_t)0;

    dim3 blk(256);
    int gx = (M + 127) / 128;
    int nb = (M + 255) / 256;
    int npair = M * D / 2;
    int cvb = (npair + 255) / 256;
    int e4 = (E + 3) / 4;

    // fork: CSR chain on side stream, overlapped with prep + QKV
    cudaEventRecord(g_e0, 0);
    cudaStreamWaitEvent(s1, g_e0, 0);

    zero_cursor<<<nb, 256, 0, s1>>>(M);
    hist_kernel<<<(e4 + 255) / 256, 256, 0, s1>>>(dst, E);
    scan_local<<<nb, 256, 0, s1>>>(M);
    scan_final<<<nb, 256, 0, s1>>>(M, E);
    scatter_kernel<<<(e4 + 255) / 256, 256, 0, s1>>>(src, dst, E);
    cudaEventRecord(g_e1, s1);

    prep_kernel<<<cvb, 256>>>(h, WQ, WK, WV, WO, W1, W2, npair);
    qkv_kernel<<<dim3(gx, 3), blk, DSMEM_BYTES>>>(M);

    cudaStreamWaitEvent(0, g_e1, 0);

    gather_kernel<<<(M * 32 + 255) / 256, 256>>>(M);

    // O projection: attn @ WO^T + bO + h(fp16) -> x1 fp16 (+ BN1 stats)
    tgemm_k<EPI_RESID, true, true, 128><<<dim3(gx, 1), blk, DSMEM_BYTES>>>(
        (const __half*)attnp, wp + OFF_WO, bO, hhp,
        stp, stp + D, nullptr, x1hp, M, D);

    bn_convert<<<cvb, 256>>>(x1hp, stp, stp + D, bn1g, bn1b, npair, M);

    // fused FFN: mid in smem, x2 = relu(bx1@W1^T+b1)@W2^T + b2 + bx1 (+ BN2 stats)
    ffn_kernel<<<gx, blk, DSMEM_FFN>>>(b1, b2, stp + 2 * D, stp + 3 * D, x2p, M);

    bn_apply<<<1024, 256>>>(x2p, stp + 2 * D, stp + 3 * D, bn2g, bn2b, out, M);
}